// round 4
// baseline (speedup 1.0000x reference)
#include <cuda_runtime.h>
#include <math.h>
#include <stdint.h>

#define HW 4096
#define CC 768
#define NHEADS 12
#define HD 64
#define SP 68   // smem row stride in floats (272B, 16B-aligned, bank-spreading)

// ---------------- scratch ----------------------------------------------------
// g_Q/g_K/g_V hold tf32-ROUNDED values (rounded once in the proj epilogue).
__device__ float g_Q[(size_t)NHEADS * HW * HD];
__device__ float g_K[(size_t)NHEADS * HW * HD];
__device__ float g_V[(size_t)NHEADS * HW * HD];
__device__ float g_relh[(size_t)NHEADS * HD * HW];  // TRANSPOSED: [head][kh][tok]
__device__ float g_relw[(size_t)NHEADS * HW * HD];  // [head][tok][kw]
__device__ float g_att[(size_t)HW * CC];

// ---------------- helpers ----------------------------------------------------
__device__ __forceinline__ float f2tf(float x) {
    uint32_t u;
    asm("cvt.rna.tf32.f32 %0, %1;" : "=r"(u) : "f"(x));
    return __uint_as_float(u);
}

__device__ __forceinline__ void mma8(float* c,
                                     uint32_t a0, uint32_t a1, uint32_t a2, uint32_t a3,
                                     uint32_t b0, uint32_t b1) {
    asm volatile(
        "mma.sync.aligned.m16n8k8.row.col.f32.tf32.tf32.f32 "
        "{%0,%1,%2,%3}, {%4,%5,%6,%7}, {%8,%9}, {%0,%1,%2,%3};\n"
        : "+f"(c[0]), "+f"(c[1]), "+f"(c[2]), "+f"(c[3])
        : "r"(a0), "r"(a1), "r"(a2), "r"(a3), "r"(b0), "r"(b1));
}
#define FU(x) __float_as_uint(x)

// ---------------- projection GEMM (tf32 mma): Y = X @ W^T + b ----------------
// tile 128(m) x 64(n), K=768 in 12 chunks of 64. Block 256 thr = 8 warps.
// DEST 0..2: epilogue rounds result to tf32 before storing to g_Q/g_K/g_V.
template <int DEST>
__global__ void __launch_bounds__(256, 2) projmma_kernel(
    const float* __restrict__ Xin, const float* __restrict__ W,
    const float* __restrict__ bias, float* __restrict__ Yout)
{
    extern __shared__ float sm[];
    float* Xs = sm;              // [128][SP]
    float* Ws = sm + 128 * SP;   // [64][SP]
    const float* X = (DEST == 3) ? (const float*)g_att : Xin;

    int tid = threadIdx.x;
    int warp = tid >> 5, lane = tid & 31, g = lane >> 2, c4 = lane & 3;
    int m0 = blockIdx.y * 128, n0 = blockIdx.x * 64;
    int r0 = warp * 16 + g, r1 = r0 + 8;

    float acc[8][4] = {};

    for (int k0 = 0; k0 < CC; k0 += 64) {
        __syncthreads();
        #pragma unroll
        for (int i = 0; i < 8; i++) {                 // X: 128x64 = 2048 float4
            int idx = tid + i * 256;
            int row = idx >> 4, j = idx & 15;
            float4 v = *(const float4*)(X + (size_t)(m0 + row) * CC + k0 + 4 * j);
            float4 t = make_float4(f2tf(v.x), f2tf(v.y), f2tf(v.z), f2tf(v.w));
            *(float4*)(Xs + row * SP + 4 * j) = t;
        }
        #pragma unroll
        for (int i = 0; i < 4; i++) {                 // W: 64x64 = 1024 float4
            int idx = tid + i * 256;
            int row = idx >> 4, j = idx & 15;
            float4 v = *(const float4*)(W + (size_t)(n0 + row) * CC + k0 + 4 * j);
            float4 t = make_float4(f2tf(v.x), f2tf(v.y), f2tf(v.z), f2tf(v.w));
            *(float4*)(Ws + row * SP + 4 * j) = t;
        }
        __syncthreads();

        #pragma unroll
        for (int s = 0; s < 8; s++) {
            int kb = 8 * s + 2 * c4;
            float2 a0 = *(const float2*)(Xs + r0 * SP + kb);
            float2 a1 = *(const float2*)(Xs + r1 * SP + kb);
            #pragma unroll
            for (int n = 0; n < 8; n++) {
                float2 b = *(const float2*)(Ws + (8 * n + g) * SP + kb);
                mma8(acc[n], FU(a0.x), FU(a1.x), FU(a0.y), FU(a1.y),
                     FU(b.x), FU(b.y));
            }
        }
    }

    #pragma unroll
    for (int n = 0; n < 8; n++) {
        int col = n0 + 8 * n + 2 * c4;
        float b0v = bias[col], b1v = bias[col + 1];
        float2 v0, v1;
        if (DEST == 3) {
            v0 = make_float2(acc[n][0] + b0v, acc[n][1] + b1v);
            v1 = make_float2(acc[n][2] + b0v, acc[n][3] + b1v);
        } else {  // round once here so attention never converts
            v0 = make_float2(f2tf(acc[n][0] + b0v), f2tf(acc[n][1] + b1v));
            v1 = make_float2(f2tf(acc[n][2] + b0v), f2tf(acc[n][3] + b1v));
        }
        int mr0 = m0 + r0, mr1 = m0 + r1;
        if (DEST == 0) {
            *(float2*)(g_Q + ((size_t)(col >> 6) * HW + mr0) * HD + (col & 63)) = v0;
            *(float2*)(g_Q + ((size_t)(col >> 6) * HW + mr1) * HD + (col & 63)) = v1;
        } else if (DEST == 1) {
            *(float2*)(g_K + ((size_t)(col >> 6) * HW + mr0) * HD + (col & 63)) = v0;
            *(float2*)(g_K + ((size_t)(col >> 6) * HW + mr1) * HD + (col & 63)) = v1;
        } else if (DEST == 2) {
            *(float2*)(g_V + ((size_t)(col >> 6) * HW + mr0) * HD + (col & 63)) = v0;
            *(float2*)(g_V + ((size_t)(col >> 6) * HW + mr1) * HD + (col & 63)) = v1;
        } else {
            *(float2*)(Yout + (size_t)mr0 * CC + col) = v0;
            *(float2*)(Yout + (size_t)mr1 * CC + col) = v1;
        }
    }
}

// ---------------- decomposed rel-pos bias (FFMA, small) ----------------------
__global__ void __launch_bounds__(256) relpos_kernel(
    const float* __restrict__ rph, const float* __restrict__ rpw)
{
    __shared__ float Qs[64][65];
    __shared__ float Rs[64][65];
    int axis = blockIdx.z, head = blockIdx.y, a0 = blockIdx.x;
    int tid = threadIdx.x, tx = tid & 15, ty = tid >> 4;
    int lr = tid >> 2, lc = (tid & 3) * 4;

    int tok_l = (axis == 0) ? (a0 * 64 + lr) : (lr * 64 + a0);
    const float* rp = (axis == 0) ? rph : rpw;
    #pragma unroll
    for (int c0 = 0; c0 < 64; c0 += 16) {
        int c = lc + c0;
        float4 qv = *(const float4*)&g_Q[((size_t)head * HW + tok_l) * HD + c];
        Qs[lr][c + 0] = qv.x; Qs[lr][c + 1] = qv.y;
        Qs[lr][c + 2] = qv.z; Qs[lr][c + 3] = qv.w;
        float4 rv = *(const float4*)&rp[(size_t)(a0 - lr + 63) * HD + c];
        Rs[lr][c + 0] = rv.x; Rs[lr][c + 1] = rv.y;
        Rs[lr][c + 2] = rv.z; Rs[lr][c + 3] = rv.w;
    }
    __syncthreads();

    float acc[4][4] = {};
    #pragma unroll
    for (int d = 0; d < 64; d++) {
        float a[4], b[4];
        #pragma unroll
        for (int i = 0; i < 4; i++) a[i] = Qs[ty + i * 16][d];
        #pragma unroll
        for (int j = 0; j < 4; j++) b[j] = Rs[tx + j * 16][d];
        #pragma unroll
        for (int i = 0; i < 4; i++)
            #pragma unroll
            for (int j = 0; j < 4; j++)
                acc[i][j] = fmaf(a[i], b[j], acc[i][j]);
    }

    #pragma unroll
    for (int i = 0; i < 4; i++) {
        int r = ty + i * 16;
        int tok = (axis == 0) ? (a0 * 64 + r) : (r * 64 + a0);
        #pragma unroll
        for (int j = 0; j < 4; j++) {
            int k = tx + j * 16;
            if (axis == 0)
                g_relh[((size_t)head * HD + k) * HW + tok] = acc[i][j];
            else
                g_relw[((size_t)head * HW + tok) * HD + k] = acc[i][j];
        }
    }
}

// ---------------- flash attention, tf32 mma, P in registers ------------------
// Inputs are pre-rounded tf32; staging is pure copy (Q scaled by exact 0.125).
__global__ void __launch_bounds__(256, 2) attnmma_kernel()
{
    extern __shared__ float sm[];
    float* Qs  = sm;                  // [128][SP] tf32, prescaled by 0.125
    float* Ks  = Qs + 128 * SP;       // [64][SP]  tf32
    float* Vt  = Ks + 64 * SP;        // [64][SP]  tf32, TRANSPOSED: [d][key]
    float* Bws = Vt + 64 * SP;        // [128][SP] f32 rel_w bias
    float* Bhs = Bws + 128 * SP;      // [128] f32 rel_h column for this key tile

    int tid = threadIdx.x;
    int warp = tid >> 5, lane = tid & 31, g = lane >> 2, c4 = lane & 3;
    int head = blockIdx.y, q0 = blockIdx.x * 128;
    int r0 = warp * 16 + g, r1 = r0 + 8;

    size_t qb = (size_t)head * HW + q0;
    #pragma unroll
    for (int i = 0; i < 8; i++) {
        int idx = tid + i * 256;
        int row = idx >> 4, j = idx & 15;
        float4 v = *(const float4*)(g_Q + (qb + row) * HD + 4 * j);
        // 0.125 is a power of two: exact on tf32 values, no re-round needed.
        *(float4*)(Qs + row * SP + 4 * j) =
            make_float4(v.x * 0.125f, v.y * 0.125f, v.z * 0.125f, v.w * 0.125f);
        float4 w = *(const float4*)(g_relw + (qb + row) * HD + 4 * j);
        *(float4*)(Bws + row * SP + 4 * j) = w;
    }

    float O[8][4] = {};
    float m0r = -INFINITY, m1r = -INFINITY, l0 = 0.f, l1 = 0.f;

    for (int kt = 0; kt < HW / 64; kt++) {
        __syncthreads();  // previous iter's Ks/Vt/Bhs readers done
        size_t kb = (size_t)head * HW + kt * 64;
        #pragma unroll
        for (int i = 0; i < 4; i++) {                 // K: coalesced copy
            int idx = tid + i * 256;
            int row = idx >> 4, j = idx & 15;
            *(float4*)(Ks + row * SP + 4 * j) =
                *(const float4*)(g_K + (kb + row) * HD + 4 * j);
        }
        #pragma unroll
        for (int i = 0; i < 4; i++) {                 // V: transpose-scatter
            int idx = tid + i * 256;
            int key = idx & 63, j = idx >> 6;
            float4 v = *(const float4*)(g_V + (kb + key) * HD + 4 * j);
            Vt[(4 * j + 0) * SP + key] = v.x;
            Vt[(4 * j + 1) * SP + key] = v.y;
            Vt[(4 * j + 2) * SP + key] = v.z;
            Vt[(4 * j + 3) * SP + key] = v.w;
        }
        if (tid < 128)
            Bhs[tid] = g_relh[((size_t)head * HD + kt) * HW + q0 + tid];
        __syncthreads();

        // ---- S = (Q/8) @ K^T + bias ----
        float S[8][4];
        float bh0 = Bhs[r0], bh1 = Bhs[r1];
        #pragma unroll
        for (int n = 0; n < 8; n++) {
            int col = 8 * n + 2 * c4;
            float2 w0 = *(const float2*)(Bws + r0 * SP + col);
            float2 w1 = *(const float2*)(Bws + r1 * SP + col);
            S[n][0] = bh0 + w0.x; S[n][1] = bh0 + w0.y;
            S[n][2] = bh1 + w1.x; S[n][3] = bh1 + w1.y;
        }
        #pragma unroll
        for (int s = 0; s < 8; s++) {
            int kb8 = 8 * s + 2 * c4;
            float2 a0 = *(const float2*)(Qs + r0 * SP + kb8);
            float2 a1 = *(const float2*)(Qs + r1 * SP + kb8);
            #pragma unroll
            for (int n = 0; n < 8; n++) {
                float2 b = *(const float2*)(Ks + (8 * n + g) * SP + kb8);
                mma8(S[n], FU(a0.x), FU(a1.x), FU(a0.y), FU(a1.y),
                     FU(b.x), FU(b.y));
            }
        }

        // ---- online softmax (rows private to quad) ----
        float mx0 = -INFINITY, mx1 = -INFINITY;
        #pragma unroll
        for (int n = 0; n < 8; n++) {
            mx0 = fmaxf(mx0, fmaxf(S[n][0], S[n][1]));
            mx1 = fmaxf(mx1, fmaxf(S[n][2], S[n][3]));
        }
        mx0 = fmaxf(mx0, __shfl_xor_sync(0xffffffffu, mx0, 1));
        mx0 = fmaxf(mx0, __shfl_xor_sync(0xffffffffu, mx0, 2));
        mx1 = fmaxf(mx1, __shfl_xor_sync(0xffffffffu, mx1, 1));
        mx1 = fmaxf(mx1, __shfl_xor_sync(0xffffffffu, mx1, 2));
        float nm0 = fmaxf(m0r, mx0), nm1 = fmaxf(m1r, mx1);
        float al0 = __expf(m0r - nm0), al1 = __expf(m1r - nm1);
        m0r = nm0; m1r = nm1;
        float s0 = 0.f, s1 = 0.f;
        #pragma unroll
        for (int n = 0; n < 8; n++) {
            float p00 = f2tf(__expf(S[n][0] - nm0));
            float p01 = f2tf(__expf(S[n][1] - nm0));
            float p10 = f2tf(__expf(S[n][2] - nm1));
            float p11 = f2tf(__expf(S[n][3] - nm1));
            s0 += p00 + p01; s1 += p10 + p11;
            S[n][0] = p00; S[n][1] = p01; S[n][2] = p10; S[n][3] = p11;
            O[n][0] *= al0; O[n][1] *= al0; O[n][2] *= al1; O[n][3] *= al1;
        }
        s0 += __shfl_xor_sync(0xffffffffu, s0, 1);
        s0 += __shfl_xor_sync(0xffffffffu, s0, 2);
        s1 += __shfl_xor_sync(0xffffffffu, s1, 1);
        s1 += __shfl_xor_sync(0xffffffffu, s1, 2);
        l0 = l0 * al0 + s0;
        l1 = l1 * al1 + s1;

        // ---- O += P @ V : A-frags directly from S registers ----
        #pragma unroll
        for (int s = 0; s < 8; s++) {
            uint32_t a0 = FU(S[s][0]), a1 = FU(S[s][2]);
            uint32_t a2 = FU(S[s][1]), a3 = FU(S[s][3]);
            int kb8 = 8 * s + 2 * c4;
            #pragma unroll
            for (int n = 0; n < 8; n++) {
                float2 b = *(const float2*)(Vt + (8 * n + g) * SP + kb8);
                mma8(O[n], a0, a1, a2, a3, FU(b.x), FU(b.y));
            }
        }
    }

    float inv0 = 1.0f / l0, inv1 = 1.0f / l1;
    #pragma unroll
    for (int n = 0; n < 8; n++) {
        int d = 8 * n + 2 * c4;
        *(float2*)(g_att + (size_t)(q0 + r0) * CC + head * HD + d) =
            make_float2(O[n][0] * inv0, O[n][1] * inv0);
        *(float2*)(g_att + (size_t)(q0 + r1) * CC + head * HD + d) =
            make_float2(O[n][2] * inv1, O[n][3] * inv1);
    }
}

// ---------------- launch -----------------------------------------------------
extern "C" void kernel_launch(void* const* d_in, const int* in_sizes, int n_in,
                              void* d_out, int out_size)
{
    const float* hs  = (const float*)d_in[0];
    const float* w_q = (const float*)d_in[1];
    const float* b_q = (const float*)d_in[2];
    const float* w_k = (const float*)d_in[3];
    const float* b_k = (const float*)d_in[4];
    const float* w_v = (const float*)d_in[5];
    const float* b_v = (const float*)d_in[6];
    const float* w_o = (const float*)d_in[7];
    const float* b_o = (const float*)d_in[8];
    const float* rph = (const float*)d_in[9];
    const float* rpw = (const float*)d_in[10];
    float* out = (float*)d_out;

    int proj_smem = (128 * SP + 64 * SP) * (int)sizeof(float);           // 52224 B
    int att_smem  = (128 * SP + 64 * SP * 2 + 128 * SP + 128) * (int)sizeof(float);  // 104960 B

    cudaFuncSetAttribute(projmma_kernel<0>, cudaFuncAttributeMaxDynamicSharedMemorySize, proj_smem);
    cudaFuncSetAttribute(projmma_kernel<1>, cudaFuncAttributeMaxDynamicSharedMemorySize, proj_smem);
    cudaFuncSetAttribute(projmma_kernel<2>, cudaFuncAttributeMaxDynamicSharedMemorySize, proj_smem);
    cudaFuncSetAttribute(projmma_kernel<3>, cudaFuncAttributeMaxDynamicSharedMemorySize, proj_smem);
    cudaFuncSetAttribute(attnmma_kernel, cudaFuncAttributeMaxDynamicSharedMemorySize, att_smem);

    dim3 gproj(CC / 64, HW / 128);  // (12, 32)
    projmma_kernel<0><<<gproj, 256, proj_smem>>>(hs, w_q, b_q, nullptr);
    projmma_kernel<1><<<gproj, 256, proj_smem>>>(hs, w_k, b_k, nullptr);
    projmma_kernel<2><<<gproj, 256, proj_smem>>>(hs, w_v, b_v, nullptr);

    relpos_kernel<<<dim3(64, NHEADS, 2), 256>>>(rph, rpw);

    attnmma_kernel<<<dim3(HW / 128, NHEADS), 256, att_smem>>>();

    projmma_kernel<3><<<gproj, 256, proj_smem>>>(nullptr, w_o, b_o, out);
}

// round 6
// speedup vs baseline: 1.3857x; 1.3857x over previous
#include <cuda_runtime.h>
#include <math.h>
#include <stdint.h>

#define HW 4096
#define CC 768
#define NHEADS 12
#define HD 64
#define SP 72   // smem row stride in floats: SP/2 ≡ 4 (mod 16) -> LDS.64 conflict-free

// ---------------- scratch ----------------------------------------------------
// g_Q/g_K/g_V hold tf32-ROUNDED values (rounded once in the proj epilogue).
__device__ float g_Q[(size_t)NHEADS * HW * HD];
__device__ float g_K[(size_t)NHEADS * HW * HD];
__device__ float g_V[(size_t)NHEADS * HW * HD];
__device__ float g_relh[(size_t)NHEADS * HD * HW];  // TRANSPOSED: [head][kh][tok]
__device__ float g_relw[(size_t)NHEADS * HW * HD];  // [head][tok][kw]
__device__ float g_att[(size_t)HW * CC];

// ---------------- helpers ----------------------------------------------------
__device__ __forceinline__ float f2tf(float x) {
    uint32_t u;
    asm("cvt.rna.tf32.f32 %0, %1;" : "=r"(u) : "f"(x));
    return __uint_as_float(u);
}

__device__ __forceinline__ void mma8(float* c,
                                     uint32_t a0, uint32_t a1, uint32_t a2, uint32_t a3,
                                     uint32_t b0, uint32_t b1) {
    asm volatile(
        "mma.sync.aligned.m16n8k8.row.col.f32.tf32.tf32.f32 "
        "{%0,%1,%2,%3}, {%4,%5,%6,%7}, {%8,%9}, {%0,%1,%2,%3};\n"
        : "+f"(c[0]), "+f"(c[1]), "+f"(c[2]), "+f"(c[3])
        : "r"(a0), "r"(a1), "r"(a2), "r"(a3), "r"(b0), "r"(b1));
}
#define FU(x) __float_as_uint(x)

// ---------------- projection GEMM (tf32 mma): Y = X @ W^T + b ----------------
template <int DEST>
__global__ void __launch_bounds__(256, 2) projmma_kernel(
    const float* __restrict__ Xin, const float* __restrict__ W,
    const float* __restrict__ bias, float* __restrict__ Yout)
{
    extern __shared__ float sm[];
    float* Xs = sm;              // [128][SP]
    float* Ws = sm + 128 * SP;   // [64][SP]
    const float* X = (DEST == 3) ? (const float*)g_att : Xin;

    int tid = threadIdx.x;
    int warp = tid >> 5, lane = tid & 31, g = lane >> 2, c4 = lane & 3;
    int m0 = blockIdx.y * 128, n0 = blockIdx.x * 64;
    int r0 = warp * 16 + g, r1 = r0 + 8;

    float acc[8][4] = {};

    for (int k0 = 0; k0 < CC; k0 += 64) {
        __syncthreads();
        #pragma unroll
        for (int i = 0; i < 8; i++) {                 // X: 128x64
            int idx = tid + i * 256;
            int row = idx >> 4, j = idx & 15;
            float4 v = *(const float4*)(X + (size_t)(m0 + row) * CC + k0 + 4 * j);
            float4 t = make_float4(f2tf(v.x), f2tf(v.y), f2tf(v.z), f2tf(v.w));
            *(float4*)(Xs + row * SP + 4 * j) = t;
        }
        #pragma unroll
        for (int i = 0; i < 4; i++) {                 // W: 64x64
            int idx = tid + i * 256;
            int row = idx >> 4, j = idx & 15;
            float4 v = *(const float4*)(W + (size_t)(n0 + row) * CC + k0 + 4 * j);
            float4 t = make_float4(f2tf(v.x), f2tf(v.y), f2tf(v.z), f2tf(v.w));
            *(float4*)(Ws + row * SP + 4 * j) = t;
        }
        __syncthreads();

        #pragma unroll
        for (int s = 0; s < 8; s++) {
            int kb = 8 * s + 2 * c4;
            float2 a0 = *(const float2*)(Xs + r0 * SP + kb);
            float2 a1 = *(const float2*)(Xs + r1 * SP + kb);
            #pragma unroll
            for (int n = 0; n < 8; n++) {
                float2 b = *(const float2*)(Ws + (8 * n + g) * SP + kb);
                mma8(acc[n], FU(a0.x), FU(a1.x), FU(a0.y), FU(a1.y),
                     FU(b.x), FU(b.y));
            }
        }
    }

    #pragma unroll
    for (int n = 0; n < 8; n++) {
        int col = n0 + 8 * n + 2 * c4;
        float b0v = bias[col], b1v = bias[col + 1];
        float2 v0, v1;
        if (DEST == 3) {
            v0 = make_float2(acc[n][0] + b0v, acc[n][1] + b1v);
            v1 = make_float2(acc[n][2] + b0v, acc[n][3] + b1v);
        } else {  // round once so attention never converts
            v0 = make_float2(f2tf(acc[n][0] + b0v), f2tf(acc[n][1] + b1v));
            v1 = make_float2(f2tf(acc[n][2] + b0v), f2tf(acc[n][3] + b1v));
        }
        int mr0 = m0 + r0, mr1 = m0 + r1;
        if (DEST == 0) {
            *(float2*)(g_Q + ((size_t)(col >> 6) * HW + mr0) * HD + (col & 63)) = v0;
            *(float2*)(g_Q + ((size_t)(col >> 6) * HW + mr1) * HD + (col & 63)) = v1;
        } else if (DEST == 1) {
            *(float2*)(g_K + ((size_t)(col >> 6) * HW + mr0) * HD + (col & 63)) = v0;
            *(float2*)(g_K + ((size_t)(col >> 6) * HW + mr1) * HD + (col & 63)) = v1;
        } else if (DEST == 2) {
            *(float2*)(g_V + ((size_t)(col >> 6) * HW + mr0) * HD + (col & 63)) = v0;
            *(float2*)(g_V + ((size_t)(col >> 6) * HW + mr1) * HD + (col & 63)) = v1;
        } else {
            *(float2*)(Yout + (size_t)mr0 * CC + col) = v0;
            *(float2*)(Yout + (size_t)mr1 * CC + col) = v1;
        }
    }
}

// ---------------- decomposed rel-pos bias (FFMA, small) ----------------------
__global__ void __launch_bounds__(256) relpos_kernel(
    const float* __restrict__ rph, const float* __restrict__ rpw)
{
    __shared__ float Qs[64][65];
    __shared__ float Rs[64][65];
    int axis = blockIdx.z, head = blockIdx.y, a0 = blockIdx.x;
    int tid = threadIdx.x, tx = tid & 15, ty = tid >> 4;
    int lr = tid >> 2, lc = (tid & 3) * 4;

    int tok_l = (axis == 0) ? (a0 * 64 + lr) : (lr * 64 + a0);
    const float* rp = (axis == 0) ? rph : rpw;
    #pragma unroll
    for (int c0 = 0; c0 < 64; c0 += 16) {
        int c = lc + c0;
        float4 qv = *(const float4*)&g_Q[((size_t)head * HW + tok_l) * HD + c];
        Qs[lr][c + 0] = qv.x; Qs[lr][c + 1] = qv.y;
        Qs[lr][c + 2] = qv.z; Qs[lr][c + 3] = qv.w;
        float4 rv = *(const float4*)&rp[(size_t)(a0 - lr + 63) * HD + c];
        Rs[lr][c + 0] = rv.x; Rs[lr][c + 1] = rv.y;
        Rs[lr][c + 2] = rv.z; Rs[lr][c + 3] = rv.w;
    }
    __syncthreads();

    float acc[4][4] = {};
    #pragma unroll
    for (int d = 0; d < 64; d++) {
        float a[4], b[4];
        #pragma unroll
        for (int i = 0; i < 4; i++) a[i] = Qs[ty + i * 16][d];
        #pragma unroll
        for (int j = 0; j < 4; j++) b[j] = Rs[tx + j * 16][d];
        #pragma unroll
        for (int i = 0; i < 4; i++)
            #pragma unroll
            for (int j = 0; j < 4; j++)
                acc[i][j] = fmaf(a[i], b[j], acc[i][j]);
    }

    #pragma unroll
    for (int i = 0; i < 4; i++) {
        int r = ty + i * 16;
        int tok = (axis == 0) ? (a0 * 64 + r) : (r * 64 + a0);
        #pragma unroll
        for (int j = 0; j < 4; j++) {
            int k = tx + j * 16;
            if (axis == 0)
                g_relh[((size_t)head * HD + k) * HW + tok] = acc[i][j];
            else
                g_relw[((size_t)head * HW + tok) * HD + k] = acc[i][j];
        }
    }
}

// ---------------- flash attention, tf32 mma ----------------------------------
// Register-P (no smem P), bias fully in registers, K/V register prefetch.
// smem = (128 + 64 + 64) * SP * 4 = 73728 B, occ 1, regs ~160.
__global__ void __launch_bounds__(256, 1) attnmma_kernel()
{
    extern __shared__ float sm[];
    float* Qs  = sm;                  // [128][SP] tf32, prescaled by 0.125
    float* Ks  = Qs + 128 * SP;       // [64][SP]  tf32
    float* Vt  = Ks + 64 * SP;        // [64][SP]  tf32, TRANSPOSED: [d][key]

    int tid = threadIdx.x;
    int warp = tid >> 5, lane = tid & 31, g = lane >> 2, c4 = lane & 3;
    int head = blockIdx.y, q0 = blockIdx.x * 128;
    int r0 = warp * 16 + g, r1 = r0 + 8;

    size_t qb = (size_t)head * HW + q0;
    #pragma unroll
    for (int i = 0; i < 8; i++) {
        int idx = tid + i * 256;
        int row = idx >> 4, j = idx & 15;
        float4 v = *(const float4*)(g_Q + (qb + row) * HD + 4 * j);
        // 0.125 is a power of two: exact on tf32 values.
        *(float4*)(Qs + row * SP + 4 * j) =
            make_float4(v.x * 0.125f, v.y * 0.125f, v.z * 0.125f, v.w * 0.125f);
    }

    // rel_w bias -> registers (32 floats), loaded once
    float bw[8][4];
    #pragma unroll
    for (int n = 0; n < 8; n++) {
        int col = 8 * n + 2 * c4;
        float2 w0 = *(const float2*)(g_relw + (qb + r0) * HD + col);
        float2 w1 = *(const float2*)(g_relw + (qb + r1) * HD + col);
        bw[n][0] = w0.x; bw[n][1] = w0.y; bw[n][2] = w1.x; bw[n][3] = w1.y;
    }

    // prefetch tile 0 (K rows, V transpose source, rel_h column)
    float4 pk[4], pv[4];
    float nbh0, nbh1;
    {
        size_t kb = (size_t)head * HW;
        #pragma unroll
        for (int i = 0; i < 4; i++) {
            int idx = tid + i * 256;
            pk[i] = *(const float4*)(g_K + (kb + (idx >> 4)) * HD + 4 * (idx & 15));
            pv[i] = *(const float4*)(g_V + (kb + (idx & 63)) * HD + 4 * (idx >> 6));
        }
        const float* rh = g_relh + (size_t)head * HD * HW + q0;
        nbh0 = rh[r0]; nbh1 = rh[r1];
    }

    float O[8][4] = {};
    float m0r = -INFINITY, m1r = -INFINITY, l0 = 0.f, l1 = 0.f;

    for (int kt = 0; kt < HW / 64; kt++) {
        __syncthreads();  // previous tile's readers done; buffers free
        #pragma unroll
        for (int i = 0; i < 4; i++) {                 // K: coalesced store
            int idx = tid + i * 256;
            *(float4*)(Ks + (idx >> 4) * SP + 4 * (idx & 15)) = pk[i];
        }
        #pragma unroll
        for (int i = 0; i < 4; i++) {                 // V: transpose-scatter
            int idx = tid + i * 256;
            int key = idx & 63, j = idx >> 6;
            Vt[(4 * j + 0) * SP + key] = pv[i].x;
            Vt[(4 * j + 1) * SP + key] = pv[i].y;
            Vt[(4 * j + 2) * SP + key] = pv[i].z;
            Vt[(4 * j + 3) * SP + key] = pv[i].w;
        }
        float bh0 = nbh0, bh1 = nbh1;
        __syncthreads();

        if (kt + 1 < HW / 64) {                       // prefetch next tile
            size_t kb = (size_t)head * HW + (kt + 1) * 64;
            #pragma unroll
            for (int i = 0; i < 4; i++) {
                int idx = tid + i * 256;
                pk[i] = *(const float4*)(g_K + (kb + (idx >> 4)) * HD + 4 * (idx & 15));
                pv[i] = *(const float4*)(g_V + (kb + (idx & 63)) * HD + 4 * (idx >> 6));
            }
            const float* rh = g_relh + ((size_t)head * HD + kt + 1) * HW + q0;
            nbh0 = rh[r0]; nbh1 = rh[r1];
        }

        // ---- S = (Q/8) @ K^T + bias ----
        float S[8][4];
        #pragma unroll
        for (int n = 0; n < 8; n++) {
            S[n][0] = bh0 + bw[n][0]; S[n][1] = bh0 + bw[n][1];
            S[n][2] = bh1 + bw[n][2]; S[n][3] = bh1 + bw[n][3];
        }
        #pragma unroll
        for (int s = 0; s < 8; s++) {
            int kb8 = 8 * s + 2 * c4;
            float2 a0 = *(const float2*)(Qs + r0 * SP + kb8);
            float2 a1 = *(const float2*)(Qs + r1 * SP + kb8);
            #pragma unroll
            for (int n = 0; n < 8; n++) {
                float2 b = *(const float2*)(Ks + (8 * n + g) * SP + kb8);
                mma8(S[n], FU(a0.x), FU(a1.x), FU(a0.y), FU(a1.y),
                     FU(b.x), FU(b.y));
            }
        }

        // ---- online softmax (rows private to quad) ----
        float mx0 = -INFINITY, mx1 = -INFINITY;
        #pragma unroll
        for (int n = 0; n < 8; n++) {
            mx0 = fmaxf(mx0, fmaxf(S[n][0], S[n][1]));
            mx1 = fmaxf(mx1, fmaxf(S[n][2], S[n][3]));
        }
        mx0 = fmaxf(mx0, __shfl_xor_sync(0xffffffffu, mx0, 1));
        mx0 = fmaxf(mx0, __shfl_xor_sync(0xffffffffu, mx0, 2));
        mx1 = fmaxf(mx1, __shfl_xor_sync(0xffffffffu, mx1, 1));
        mx1 = fmaxf(mx1, __shfl_xor_sync(0xffffffffu, mx1, 2));
        float nm0 = fmaxf(m0r, mx0), nm1 = fmaxf(m1r, mx1);
        float al0 = __expf(m0r - nm0), al1 = __expf(m1r - nm1);
        m0r = nm0; m1r = nm1;
        float s0 = 0.f, s1 = 0.f;
        #pragma unroll
        for (int n = 0; n < 8; n++) {
            float p00 = f2tf(__expf(S[n][0] - nm0));
            float p01 = f2tf(__expf(S[n][1] - nm0));
            float p10 = f2tf(__expf(S[n][2] - nm1));
            float p11 = f2tf(__expf(S[n][3] - nm1));
            s0 += p00 + p01; s1 += p10 + p11;
            S[n][0] = p00; S[n][1] = p01; S[n][2] = p10; S[n][3] = p11;
            O[n][0] *= al0; O[n][1] *= al0; O[n][2] *= al1; O[n][3] *= al1;
        }
        s0 += __shfl_xor_sync(0xffffffffu, s0, 1);
        s0 += __shfl_xor_sync(0xffffffffu, s0, 2);
        s1 += __shfl_xor_sync(0xffffffffu, s1, 1);
        s1 += __shfl_xor_sync(0xffffffffu, s1, 2);
        l0 = l0 * al0 + s0;
        l1 = l1 * al1 + s1;

        // ---- O += P @ V : A-frags directly from S registers ----
        #pragma unroll
        for (int s = 0; s < 8; s++) {
            uint32_t a0 = FU(S[s][0]), a1 = FU(S[s][2]);
            uint32_t a2 = FU(S[s][1]), a3 = FU(S[s][3]);
            int kb8 = 8 * s + 2 * c4;
            #pragma unroll
            for (int n = 0; n < 8; n++) {
                float2 b = *(const float2*)(Vt + (8 * n + g) * SP + kb8);
                mma8(O[n], a0, a1, a2, a3, FU(b.x), FU(b.y));
            }
        }
    }

    float inv0 = 1.0f / l0, inv1 = 1.0f / l1;
    #pragma unroll
    for (int n = 0; n < 8; n++) {
        int d = 8 * n + 2 * c4;
        *(float2*)(g_att + (size_t)(q0 + r0) * CC + head * HD + d) =
            make_float2(O[n][0] * inv0, O[n][1] * inv0);
        *(float2*)(g_att + (size_t)(q0 + r1) * CC + head * HD + d) =
            make_float2(O[n][2] * inv1, O[n][3] * inv1);
    }
}

// ---------------- launch -----------------------------------------------------
extern "C" void kernel_launch(void* const* d_in, const int* in_sizes, int n_in,
                              void* d_out, int out_size)
{
    const float* hs  = (const float*)d_in[0];
    const float* w_q = (const float*)d_in[1];
    const float* b_q = (const float*)d_in[2];
    const float* w_k = (const float*)d_in[3];
    const float* b_k = (const float*)d_in[4];
    const float* w_v = (const float*)d_in[5];
    const float* b_v = (const float*)d_in[6];
    const float* w_o = (const float*)d_in[7];
    const float* b_o = (const float*)d_in[8];
    const float* rph = (const float*)d_in[9];
    const float* rpw = (const float*)d_in[10];
    float* out = (float*)d_out;

    int proj_smem = (128 * SP + 64 * SP) * (int)sizeof(float);   // 55296 B
    int att_smem  = (128 * SP + 64 * SP * 2) * (int)sizeof(float);  // 73728 B

    cudaFuncSetAttribute(projmma_kernel<0>, cudaFuncAttributeMaxDynamicSharedMemorySize, proj_smem);
    cudaFuncSetAttribute(projmma_kernel<1>, cudaFuncAttributeMaxDynamicSharedMemorySize, proj_smem);
    cudaFuncSetAttribute(projmma_kernel<2>, cudaFuncAttributeMaxDynamicSharedMemorySize, proj_smem);
    cudaFuncSetAttribute(projmma_kernel<3>, cudaFuncAttributeMaxDynamicSharedMemorySize, proj_smem);
    cudaFuncSetAttribute(attnmma_kernel, cudaFuncAttributeMaxDynamicSharedMemorySize, att_smem);

    dim3 gproj(CC / 64, HW / 128);  // (12, 32)
    projmma_kernel<0><<<gproj, 256, proj_smem>>>(hs, w_q, b_q, nullptr);
    projmma_kernel<1><<<gproj, 256, proj_smem>>>(hs, w_k, b_k, nullptr);
    projmma_kernel<2><<<gproj, 256, proj_smem>>>(hs, w_v, b_v, nullptr);

    relpos_kernel<<<dim3(64, NHEADS, 2), 256>>>(rph, rpw);

    attnmma_kernel<<<dim3(HW / 128, NHEADS), 256, att_smem>>>();

    projmma_kernel<3><<<gproj, 256, proj_smem>>>(nullptr, w_o, b_o, out);
}

// round 7
// speedup vs baseline: 1.3926x; 1.0050x over previous
#include <cuda_runtime.h>
#include <math.h>
#include <stdint.h>

#define HW 4096
#define CC 768
#define NHEADS 12
#define HD 64
#define SP 72   // smem row stride in floats: SP/2 ≡ 4 (mod 16) -> LDS.64 conflict-free

// ---------------- scratch ----------------------------------------------------
// g_Q/g_K/g_V hold tf32-ROUNDED values (rounded once in the proj epilogue).
__device__ float g_Q[(size_t)NHEADS * HW * HD];
__device__ float g_K[(size_t)NHEADS * HW * HD];
__device__ float g_V[(size_t)NHEADS * HW * HD];
__device__ float g_relh[(size_t)NHEADS * HD * HW];  // TRANSPOSED: [head][kh][tok]
__device__ float g_relw[(size_t)NHEADS * HW * HD];  // [head][tok][kw]
__device__ float g_att[(size_t)HW * CC];

// ---------------- helpers ----------------------------------------------------
__device__ __forceinline__ float f2tf(float x) {
    uint32_t u;
    asm("cvt.rna.tf32.f32 %0, %1;" : "=r"(u) : "f"(x));
    return __uint_as_float(u);
}

__device__ __forceinline__ float ex2f(float x) {
    float y;
    asm("ex2.approx.f32 %0, %1;" : "=f"(y) : "f"(x));
    return y;
}

__device__ __forceinline__ void mma8(float* c,
                                     uint32_t a0, uint32_t a1, uint32_t a2, uint32_t a3,
                                     uint32_t b0, uint32_t b1) {
    asm volatile(
        "mma.sync.aligned.m16n8k8.row.col.f32.tf32.tf32.f32 "
        "{%0,%1,%2,%3}, {%4,%5,%6,%7}, {%8,%9}, {%0,%1,%2,%3};\n"
        : "+f"(c[0]), "+f"(c[1]), "+f"(c[2]), "+f"(c[3])
        : "r"(a0), "r"(a1), "r"(a2), "r"(a3), "r"(b0), "r"(b1));
}
#define FU(x) __float_as_uint(x)

// ---------------- projection GEMM (tf32 mma): Y = X @ W^T + b ----------------
template <int DEST>
__global__ void __launch_bounds__(256, 2) projmma_kernel(
    const float* __restrict__ Xin, const float* __restrict__ W,
    const float* __restrict__ bias, float* __restrict__ Yout)
{
    extern __shared__ float sm[];
    float* Xs = sm;              // [128][SP]
    float* Ws = sm + 128 * SP;   // [64][SP]
    const float* X = (DEST == 3) ? (const float*)g_att : Xin;

    int tid = threadIdx.x;
    int warp = tid >> 5, lane = tid & 31, g = lane >> 2, c4 = lane & 3;
    int m0 = blockIdx.y * 128, n0 = blockIdx.x * 64;
    int r0 = warp * 16 + g, r1 = r0 + 8;

    float acc[8][4] = {};

    for (int k0 = 0; k0 < CC; k0 += 64) {
        __syncthreads();
        #pragma unroll
        for (int i = 0; i < 8; i++) {                 // X: 128x64
            int idx = tid + i * 256;
            int row = idx >> 4, j = idx & 15;
            float4 v = *(const float4*)(X + (size_t)(m0 + row) * CC + k0 + 4 * j);
            float4 t = make_float4(f2tf(v.x), f2tf(v.y), f2tf(v.z), f2tf(v.w));
            *(float4*)(Xs + row * SP + 4 * j) = t;
        }
        #pragma unroll
        for (int i = 0; i < 4; i++) {                 // W: 64x64
            int idx = tid + i * 256;
            int row = idx >> 4, j = idx & 15;
            float4 v = *(const float4*)(W + (size_t)(n0 + row) * CC + k0 + 4 * j);
            float4 t = make_float4(f2tf(v.x), f2tf(v.y), f2tf(v.z), f2tf(v.w));
            *(float4*)(Ws + row * SP + 4 * j) = t;
        }
        __syncthreads();

        #pragma unroll
        for (int s = 0; s < 8; s++) {
            int kb = 8 * s + 2 * c4;
            float2 a0 = *(const float2*)(Xs + r0 * SP + kb);
            float2 a1 = *(const float2*)(Xs + r1 * SP + kb);
            #pragma unroll
            for (int n = 0; n < 8; n++) {
                float2 b = *(const float2*)(Ws + (8 * n + g) * SP + kb);
                mma8(acc[n], FU(a0.x), FU(a1.x), FU(a0.y), FU(a1.y),
                     FU(b.x), FU(b.y));
            }
        }
    }

    #pragma unroll
    for (int n = 0; n < 8; n++) {
        int col = n0 + 8 * n + 2 * c4;
        float b0v = bias[col], b1v = bias[col + 1];
        float2 v0, v1;
        if (DEST == 3) {
            v0 = make_float2(acc[n][0] + b0v, acc[n][1] + b1v);
            v1 = make_float2(acc[n][2] + b0v, acc[n][3] + b1v);
        } else {  // round once so attention never converts
            v0 = make_float2(f2tf(acc[n][0] + b0v), f2tf(acc[n][1] + b1v));
            v1 = make_float2(f2tf(acc[n][2] + b0v), f2tf(acc[n][3] + b1v));
        }
        int mr0 = m0 + r0, mr1 = m0 + r1;
        if (DEST == 0) {
            *(float2*)(g_Q + ((size_t)(col >> 6) * HW + mr0) * HD + (col & 63)) = v0;
            *(float2*)(g_Q + ((size_t)(col >> 6) * HW + mr1) * HD + (col & 63)) = v1;
        } else if (DEST == 1) {
            *(float2*)(g_K + ((size_t)(col >> 6) * HW + mr0) * HD + (col & 63)) = v0;
            *(float2*)(g_K + ((size_t)(col >> 6) * HW + mr1) * HD + (col & 63)) = v1;
        } else if (DEST == 2) {
            *(float2*)(g_V + ((size_t)(col >> 6) * HW + mr0) * HD + (col & 63)) = v0;
            *(float2*)(g_V + ((size_t)(col >> 6) * HW + mr1) * HD + (col & 63)) = v1;
        } else {
            *(float2*)(Yout + (size_t)mr0 * CC + col) = v0;
            *(float2*)(Yout + (size_t)mr1 * CC + col) = v1;
        }
    }
}

// ---------------- decomposed rel-pos bias (FFMA, small) ----------------------
__global__ void __launch_bounds__(256) relpos_kernel(
    const float* __restrict__ rph, const float* __restrict__ rpw)
{
    __shared__ float Qs[64][65];
    __shared__ float Rs[64][65];
    int axis = blockIdx.z, head = blockIdx.y, a0 = blockIdx.x;
    int tid = threadIdx.x, tx = tid & 15, ty = tid >> 4;
    int lr = tid >> 2, lc = (tid & 3) * 4;

    int tok_l = (axis == 0) ? (a0 * 64 + lr) : (lr * 64 + a0);
    const float* rp = (axis == 0) ? rph : rpw;
    #pragma unroll
    for (int c0 = 0; c0 < 64; c0 += 16) {
        int c = lc + c0;
        float4 qv = *(const float4*)&g_Q[((size_t)head * HW + tok_l) * HD + c];
        Qs[lr][c + 0] = qv.x; Qs[lr][c + 1] = qv.y;
        Qs[lr][c + 2] = qv.z; Qs[lr][c + 3] = qv.w;
        float4 rv = *(const float4*)&rp[(size_t)(a0 - lr + 63) * HD + c];
        Rs[lr][c + 0] = rv.x; Rs[lr][c + 1] = rv.y;
        Rs[lr][c + 2] = rv.z; Rs[lr][c + 3] = rv.w;
    }
    __syncthreads();

    float acc[4][4] = {};
    #pragma unroll
    for (int d = 0; d < 64; d++) {
        float a[4], b[4];
        #pragma unroll
        for (int i = 0; i < 4; i++) a[i] = Qs[ty + i * 16][d];
        #pragma unroll
        for (int j = 0; j < 4; j++) b[j] = Rs[tx + j * 16][d];
        #pragma unroll
        for (int i = 0; i < 4; i++)
            #pragma unroll
            for (int j = 0; j < 4; j++)
                acc[i][j] = fmaf(a[i], b[j], acc[i][j]);
    }

    #pragma unroll
    for (int i = 0; i < 4; i++) {
        int r = ty + i * 16;
        int tok = (axis == 0) ? (a0 * 64 + r) : (r * 64 + a0);
        #pragma unroll
        for (int j = 0; j < 4; j++) {
            int k = tx + j * 16;
            if (axis == 0)
                g_relh[((size_t)head * HD + k) * HW + tok] = acc[i][j];
            else
                g_relw[((size_t)head * HW + tok) * HD + k] = acc[i][j];
        }
    }
}

// ---------------- flash attention, tf32 mma ----------------------------------
// Register-P, bias in registers (log2e-folded), exp2 softmax, double-buffered
// K/V smem stages with ONE barrier per key tile.
// smem = (128 + 4*64) * SP * 4 = 110,592 B, occ 1.
__global__ void __launch_bounds__(256, 1) attnmma_kernel()
{
    extern __shared__ float sm[];
    float* Qs    = sm;                     // [128][SP] tf32, prescaled 0.125*log2e
    float* Kbase = Qs + 128 * SP;          // [2][64][SP]
    float* Vbase = Kbase + 2 * 64 * SP;    // [2][64][SP] transposed [d][key]

    int tid = threadIdx.x;
    int warp = tid >> 5, lane = tid & 31, g = lane >> 2, c4 = lane & 3;
    int head = blockIdx.y, q0 = blockIdx.x * 128;
    int r0 = warp * 16 + g, r1 = r0 + 8;

    const float L2E = 1.44269504f;
    const float QSC = 0.125f * L2E;

    size_t qb = (size_t)head * HW + q0;
    #pragma unroll
    for (int i = 0; i < 8; i++) {
        int idx = tid + i * 256;
        int row = idx >> 4, j = idx & 15;
        float4 v = *(const float4*)(g_Q + (qb + row) * HD + 4 * j);
        *(float4*)(Qs + row * SP + 4 * j) =
            make_float4(f2tf(v.x * QSC), f2tf(v.y * QSC),
                        f2tf(v.z * QSC), f2tf(v.w * QSC));
    }

    // rel_w bias -> registers (32 floats), scaled by log2e, loaded once
    float bw[8][4];
    #pragma unroll
    for (int n = 0; n < 8; n++) {
        int col = 8 * n + 2 * c4;
        float2 w0 = *(const float2*)(g_relw + (qb + r0) * HD + col);
        float2 w1 = *(const float2*)(g_relw + (qb + r1) * HD + col);
        bw[n][0] = w0.x * L2E; bw[n][1] = w0.y * L2E;
        bw[n][2] = w1.x * L2E; bw[n][3] = w1.y * L2E;
    }

    // load tile 0, store into stage 0 (visible after first barrier)
    float4 pk[4], pv[4];
    float nbh0, nbh1;
    {
        size_t kb = (size_t)head * HW;
        #pragma unroll
        for (int i = 0; i < 4; i++) {
            int idx = tid + i * 256;
            pk[i] = *(const float4*)(g_K + (kb + (idx >> 4)) * HD + 4 * (idx & 15));
            pv[i] = *(const float4*)(g_V + (kb + (idx & 63)) * HD + 4 * (idx >> 6));
        }
        const float* rh = g_relh + (size_t)head * HD * HW + q0;
        nbh0 = rh[r0] * L2E; nbh1 = rh[r1] * L2E;
        #pragma unroll
        for (int i = 0; i < 4; i++) {
            int idx = tid + i * 256;
            *(float4*)(Kbase + (idx >> 4) * SP + 4 * (idx & 15)) = pk[i];
            int key = idx & 63, j = idx >> 6;
            Vbase[(4 * j + 0) * SP + key] = pv[i].x;
            Vbase[(4 * j + 1) * SP + key] = pv[i].y;
            Vbase[(4 * j + 2) * SP + key] = pv[i].z;
            Vbase[(4 * j + 3) * SP + key] = pv[i].w;
        }
    }
    float cbh0 = nbh0, cbh1 = nbh1;

    float O[8][4] = {};
    float m0r = -INFINITY, m1r = -INFINITY, l0 = 0.f, l1 = 0.f;

    int p = 0;
    for (int kt = 0; kt < HW / 64; kt++) {
        // ONE barrier per tile: stage p stores visible; stage p^1 readers done.
        __syncthreads();
        const float* Ks = Kbase + p * 64 * SP;
        const float* Vt = Vbase + p * 64 * SP;

        if (kt + 1 < HW / 64) {                       // prefetch next tile -> regs
            size_t kb = (size_t)head * HW + (kt + 1) * 64;
            #pragma unroll
            for (int i = 0; i < 4; i++) {
                int idx = tid + i * 256;
                pk[i] = *(const float4*)(g_K + (kb + (idx >> 4)) * HD + 4 * (idx & 15));
                pv[i] = *(const float4*)(g_V + (kb + (idx & 63)) * HD + 4 * (idx >> 6));
            }
            const float* rh = g_relh + ((size_t)head * HD + kt + 1) * HW + q0;
            nbh0 = rh[r0] * L2E; nbh1 = rh[r1] * L2E;
        }

        // ---- S = (Q*0.125*log2e) @ K^T + bias*log2e ----
        float S[8][4];
        #pragma unroll
        for (int n = 0; n < 8; n++) {
            S[n][0] = cbh0 + bw[n][0]; S[n][1] = cbh0 + bw[n][1];
            S[n][2] = cbh1 + bw[n][2]; S[n][3] = cbh1 + bw[n][3];
        }
        #pragma unroll
        for (int s = 0; s < 8; s++) {
            int kb8 = 8 * s + 2 * c4;
            float2 a0 = *(const float2*)(Qs + r0 * SP + kb8);
            float2 a1 = *(const float2*)(Qs + r1 * SP + kb8);
            #pragma unroll
            for (int n = 0; n < 8; n++) {
                float2 b = *(const float2*)(Ks + (8 * n + g) * SP + kb8);
                mma8(S[n], FU(a0.x), FU(a1.x), FU(a0.y), FU(a1.y),
                     FU(b.x), FU(b.y));
            }
        }

        // ---- online softmax in exp2 domain (rows private to quad) ----
        float mx0 = -INFINITY, mx1 = -INFINITY;
        #pragma unroll
        for (int n = 0; n < 8; n++) {
            mx0 = fmaxf(mx0, fmaxf(S[n][0], S[n][1]));
            mx1 = fmaxf(mx1, fmaxf(S[n][2], S[n][3]));
        }
        mx0 = fmaxf(mx0, __shfl_xor_sync(0xffffffffu, mx0, 1));
        mx0 = fmaxf(mx0, __shfl_xor_sync(0xffffffffu, mx0, 2));
        mx1 = fmaxf(mx1, __shfl_xor_sync(0xffffffffu, mx1, 1));
        mx1 = fmaxf(mx1, __shfl_xor_sync(0xffffffffu, mx1, 2));
        float nm0 = fmaxf(m0r, mx0), nm1 = fmaxf(m1r, mx1);
        float al0 = ex2f(m0r - nm0), al1 = ex2f(m1r - nm1);
        m0r = nm0; m1r = nm1;
        float s0 = 0.f, s1 = 0.f;
        #pragma unroll
        for (int n = 0; n < 8; n++) {
            float p00 = f2tf(ex2f(S[n][0] - nm0));
            float p01 = f2tf(ex2f(S[n][1] - nm0));
            float p10 = f2tf(ex2f(S[n][2] - nm1));
            float p11 = f2tf(ex2f(S[n][3] - nm1));
            s0 += p00 + p01; s1 += p10 + p11;
            S[n][0] = p00; S[n][1] = p01; S[n][2] = p10; S[n][3] = p11;
            O[n][0] *= al0; O[n][1] *= al0; O[n][2] *= al1; O[n][3] *= al1;
        }
        s0 += __shfl_xor_sync(0xffffffffu, s0, 1);
        s0 += __shfl_xor_sync(0xffffffffu, s0, 2);
        s1 += __shfl_xor_sync(0xffffffffu, s1, 1);
        s1 += __shfl_xor_sync(0xffffffffu, s1, 2);
        l0 = l0 * al0 + s0;
        l1 = l1 * al1 + s1;

        // ---- O += P @ V : A-frags directly from S registers ----
        #pragma unroll
        for (int s = 0; s < 8; s++) {
            uint32_t a0 = FU(S[s][0]), a1 = FU(S[s][2]);
            uint32_t a2 = FU(S[s][1]), a3 = FU(S[s][3]);
            int kb8 = 8 * s + 2 * c4;
            #pragma unroll
            for (int n = 0; n < 8; n++) {
                float2 b = *(const float2*)(Vt + (8 * n + g) * SP + kb8);
                mma8(O[n], a0, a1, a2, a3, FU(b.x), FU(b.y));
            }
        }

        // ---- store prefetched tile into the other stage ----
        if (kt + 1 < HW / 64) {
            float* Ksn = Kbase + (p ^ 1) * 64 * SP;
            float* Vtn = Vbase + (p ^ 1) * 64 * SP;
            #pragma unroll
            for (int i = 0; i < 4; i++) {
                int idx = tid + i * 256;
                *(float4*)(Ksn + (idx >> 4) * SP + 4 * (idx & 15)) = pk[i];
                int key = idx & 63, j = idx >> 6;
                Vtn[(4 * j + 0) * SP + key] = pv[i].x;
                Vtn[(4 * j + 1) * SP + key] = pv[i].y;
                Vtn[(4 * j + 2) * SP + key] = pv[i].z;
                Vtn[(4 * j + 3) * SP + key] = pv[i].w;
            }
            cbh0 = nbh0; cbh1 = nbh1;
        }
        p ^= 1;
    }

    float inv0 = 1.0f / l0, inv1 = 1.0f / l1;
    #pragma unroll
    for (int n = 0; n < 8; n++) {
        int d = 8 * n + 2 * c4;
        *(float2*)(g_att + (size_t)(q0 + r0) * CC + head * HD + d) =
            make_float2(O[n][0] * inv0, O[n][1] * inv0);
        *(float2*)(g_att + (size_t)(q0 + r1) * CC + head * HD + d) =
            make_float2(O[n][2] * inv1, O[n][3] * inv1);
    }
}

// ---------------- launch -----------------------------------------------------
extern "C" void kernel_launch(void* const* d_in, const int* in_sizes, int n_in,
                              void* d_out, int out_size)
{
    const float* hs  = (const float*)d_in[0];
    const float* w_q = (const float*)d_in[1];
    const float* b_q = (const float*)d_in[2];
    const float* w_k = (const float*)d_in[3];
    const float* b_k = (const float*)d_in[4];
    const float* w_v = (const float*)d_in[5];
    const float* b_v = (const float*)d_in[6];
    const float* w_o = (const float*)d_in[7];
    const float* b_o = (const float*)d_in[8];
    const float* rph = (const float*)d_in[9];
    const float* rpw = (const float*)d_in[10];
    float* out = (float*)d_out;

    int proj_smem = (128 * SP + 64 * SP) * (int)sizeof(float);       // 55296 B
    int att_smem  = (128 * SP + 4 * 64 * SP) * (int)sizeof(float);   // 110592 B

    cudaFuncSetAttribute(projmma_kernel<0>, cudaFuncAttributeMaxDynamicSharedMemorySize, proj_smem);
    cudaFuncSetAttribute(projmma_kernel<1>, cudaFuncAttributeMaxDynamicSharedMemorySize, proj_smem);
    cudaFuncSetAttribute(projmma_kernel<2>, cudaFuncAttributeMaxDynamicSharedMemorySize, proj_smem);
    cudaFuncSetAttribute(projmma_kernel<3>, cudaFuncAttributeMaxDynamicSharedMemorySize, proj_smem);
    cudaFuncSetAttribute(attnmma_kernel, cudaFuncAttributeMaxDynamicSharedMemorySize, att_smem);

    dim3 gproj(CC / 64, HW / 128);  // (12, 32)
    projmma_kernel<0><<<gproj, 256, proj_smem>>>(hs, w_q, b_q, nullptr);
    projmma_kernel<1><<<gproj, 256, proj_smem>>>(hs, w_k, b_k, nullptr);
    projmma_kernel<2><<<gproj, 256, proj_smem>>>(hs, w_v, b_v, nullptr);

    relpos_kernel<<<dim3(64, NHEADS, 2), 256>>>(rph, rpw);

    attnmma_kernel<<<dim3(HW / 128, NHEADS), 256, att_smem>>>();

    projmma_kernel<3><<<gproj, 256, proj_smem>>>(nullptr, w_o, b_o, out);
}

// round 8
// speedup vs baseline: 1.4127x; 1.0144x over previous
#include <cuda_runtime.h>
#include <math.h>
#include <stdint.h>

#define HW 4096
#define CC 768
#define NHEADS 12
#define HD 64
#define SP 72   // smem row stride in floats: SP/2 ≡ 4 (mod 16) -> LDS.64 conflict-free

// ---------------- scratch ----------------------------------------------------
// g_Q/g_K/g_V hold tf32-ROUNDED values (rounded once in the proj epilogue).
__device__ float g_Q[(size_t)NHEADS * HW * HD];
__device__ float g_K[(size_t)NHEADS * HW * HD];
__device__ float g_V[(size_t)NHEADS * HW * HD];
__device__ float g_relh[(size_t)NHEADS * HD * HW];  // TRANSPOSED: [head][kh][tok]
__device__ float g_relw[(size_t)NHEADS * HW * HD];  // [head][tok][kw]
__device__ float g_att[(size_t)HW * CC];

// ---------------- helpers ----------------------------------------------------
__device__ __forceinline__ float f2tf(float x) {
    uint32_t u;
    asm("cvt.rna.tf32.f32 %0, %1;" : "=r"(u) : "f"(x));
    return __uint_as_float(u);
}

__device__ __forceinline__ float ex2f(float x) {
    float y;
    asm("ex2.approx.f32 %0, %1;" : "=f"(y) : "f"(x));
    return y;
}

__device__ __forceinline__ void mma8(float* c,
                                     uint32_t a0, uint32_t a1, uint32_t a2, uint32_t a3,
                                     uint32_t b0, uint32_t b1) {
    asm volatile(
        "mma.sync.aligned.m16n8k8.row.col.f32.tf32.tf32.f32 "
        "{%0,%1,%2,%3}, {%4,%5,%6,%7}, {%8,%9}, {%0,%1,%2,%3};\n"
        : "+f"(c[0]), "+f"(c[1]), "+f"(c[2]), "+f"(c[3])
        : "r"(a0), "r"(a1), "r"(a2), "r"(a3), "r"(b0), "r"(b1));
}
#define FU(x) __float_as_uint(x)

// ---------------- projection GEMM (tf32 mma): Y = X @ W^T + b ----------------
template <int DEST>
__global__ void __launch_bounds__(256, 2) projmma_kernel(
    const float* __restrict__ Xin, const float* __restrict__ W,
    const float* __restrict__ bias, float* __restrict__ Yout)
{
    extern __shared__ float sm[];
    float* Xs = sm;              // [128][SP]
    float* Ws = sm + 128 * SP;   // [64][SP]
    const float* X = (DEST == 3) ? (const float*)g_att : Xin;

    int tid = threadIdx.x;
    int warp = tid >> 5, lane = tid & 31, g = lane >> 2, c4 = lane & 3;
    int m0 = blockIdx.y * 128, n0 = blockIdx.x * 64;
    int r0 = warp * 16 + g, r1 = r0 + 8;

    float acc[8][4] = {};

    for (int k0 = 0; k0 < CC; k0 += 64) {
        __syncthreads();
        #pragma unroll
        for (int i = 0; i < 8; i++) {                 // X: 128x64
            int idx = tid + i * 256;
            int row = idx >> 4, j = idx & 15;
            float4 v = *(const float4*)(X + (size_t)(m0 + row) * CC + k0 + 4 * j);
            float4 t = make_float4(f2tf(v.x), f2tf(v.y), f2tf(v.z), f2tf(v.w));
            *(float4*)(Xs + row * SP + 4 * j) = t;
        }
        #pragma unroll
        for (int i = 0; i < 4; i++) {                 // W: 64x64
            int idx = tid + i * 256;
            int row = idx >> 4, j = idx & 15;
            float4 v = *(const float4*)(W + (size_t)(n0 + row) * CC + k0 + 4 * j);
            float4 t = make_float4(f2tf(v.x), f2tf(v.y), f2tf(v.z), f2tf(v.w));
            *(float4*)(Ws + row * SP + 4 * j) = t;
        }
        __syncthreads();

        #pragma unroll
        for (int s = 0; s < 8; s++) {
            int kb = 8 * s + 2 * c4;
            float2 a0 = *(const float2*)(Xs + r0 * SP + kb);
            float2 a1 = *(const float2*)(Xs + r1 * SP + kb);
            #pragma unroll
            for (int n = 0; n < 8; n++) {
                float2 b = *(const float2*)(Ws + (8 * n + g) * SP + kb);
                mma8(acc[n], FU(a0.x), FU(a1.x), FU(a0.y), FU(a1.y),
                     FU(b.x), FU(b.y));
            }
        }
    }

    #pragma unroll
    for (int n = 0; n < 8; n++) {
        int col = n0 + 8 * n + 2 * c4;
        float b0v = bias[col], b1v = bias[col + 1];
        float2 v0, v1;
        if (DEST == 3) {
            v0 = make_float2(acc[n][0] + b0v, acc[n][1] + b1v);
            v1 = make_float2(acc[n][2] + b0v, acc[n][3] + b1v);
        } else {  // round once so attention never converts
            v0 = make_float2(f2tf(acc[n][0] + b0v), f2tf(acc[n][1] + b1v));
            v1 = make_float2(f2tf(acc[n][2] + b0v), f2tf(acc[n][3] + b1v));
        }
        int mr0 = m0 + r0, mr1 = m0 + r1;
        if (DEST == 0) {
            *(float2*)(g_Q + ((size_t)(col >> 6) * HW + mr0) * HD + (col & 63)) = v0;
            *(float2*)(g_Q + ((size_t)(col >> 6) * HW + mr1) * HD + (col & 63)) = v1;
        } else if (DEST == 1) {
            *(float2*)(g_K + ((size_t)(col >> 6) * HW + mr0) * HD + (col & 63)) = v0;
            *(float2*)(g_K + ((size_t)(col >> 6) * HW + mr1) * HD + (col & 63)) = v1;
        } else if (DEST == 2) {
            *(float2*)(g_V + ((size_t)(col >> 6) * HW + mr0) * HD + (col & 63)) = v0;
            *(float2*)(g_V + ((size_t)(col >> 6) * HW + mr1) * HD + (col & 63)) = v1;
        } else {
            *(float2*)(Yout + (size_t)mr0 * CC + col) = v0;
            *(float2*)(Yout + (size_t)mr1 * CC + col) = v1;
        }
    }
}

// ---------------- decomposed rel-pos bias (FFMA, small) ----------------------
__global__ void __launch_bounds__(256) relpos_kernel(
    const float* __restrict__ rph, const float* __restrict__ rpw)
{
    __shared__ float Qs[64][65];
    __shared__ float Rs[64][65];
    int axis = blockIdx.z, head = blockIdx.y, a0 = blockIdx.x;
    int tid = threadIdx.x, tx = tid & 15, ty = tid >> 4;
    int lr = tid >> 2, lc = (tid & 3) * 4;

    int tok_l = (axis == 0) ? (a0 * 64 + lr) : (lr * 64 + a0);
    const float* rp = (axis == 0) ? rph : rpw;
    #pragma unroll
    for (int c0 = 0; c0 < 64; c0 += 16) {
        int c = lc + c0;
        float4 qv = *(const float4*)&g_Q[((size_t)head * HW + tok_l) * HD + c];
        Qs[lr][c + 0] = qv.x; Qs[lr][c + 1] = qv.y;
        Qs[lr][c + 2] = qv.z; Qs[lr][c + 3] = qv.w;
        float4 rv = *(const float4*)&rp[(size_t)(a0 - lr + 63) * HD + c];
        Rs[lr][c + 0] = rv.x; Rs[lr][c + 1] = rv.y;
        Rs[lr][c + 2] = rv.z; Rs[lr][c + 3] = rv.w;
    }
    __syncthreads();

    float acc[4][4] = {};
    #pragma unroll
    for (int d = 0; d < 64; d++) {
        float a[4], b[4];
        #pragma unroll
        for (int i = 0; i < 4; i++) a[i] = Qs[ty + i * 16][d];
        #pragma unroll
        for (int j = 0; j < 4; j++) b[j] = Rs[tx + j * 16][d];
        #pragma unroll
        for (int i = 0; i < 4; i++)
            #pragma unroll
            for (int j = 0; j < 4; j++)
                acc[i][j] = fmaf(a[i], b[j], acc[i][j]);
    }

    #pragma unroll
    for (int i = 0; i < 4; i++) {
        int r = ty + i * 16;
        int tok = (axis == 0) ? (a0 * 64 + r) : (r * 64 + a0);
        #pragma unroll
        for (int j = 0; j < 4; j++) {
            int k = tx + j * 16;
            if (axis == 0)
                g_relh[((size_t)head * HD + k) * HW + tok] = acc[i][j];
            else
                g_relw[((size_t)head * HW + tok) * HD + k] = acc[i][j];
        }
    }
}

// ---------------- flash attention, tf32 mma, occupancy 2 ---------------------
// Register-P, bias in smem (log2e-folded at store), exp2 softmax, single
// K/V buffer with two barriers/tile. smem 110,592 B -> 2 CTAs/SM,
// 16 warps/SM = 4 per SMSP for latency hiding. regs ~100 (no prefetch bufs).
__global__ void __launch_bounds__(256, 2) attnmma_kernel()
{
    extern __shared__ float sm[];
    float* Qs  = sm;                  // [128][SP] tf32, prescaled 0.125*log2e
    float* Bws = Qs + 128 * SP;       // [128][SP] rel_w bias * log2e
    float* Ks  = Bws + 128 * SP;      // [64][SP]
    float* Vt  = Ks + 64 * SP;        // [64][SP] transposed [d][key]

    int tid = threadIdx.x;
    int warp = tid >> 5, lane = tid & 31, g = lane >> 2, c4 = lane & 3;
    int head = blockIdx.y, q0 = blockIdx.x * 128;
    int r0 = warp * 16 + g, r1 = r0 + 8;

    const float L2E = 1.44269504f;
    const float QSC = 0.125f * L2E;

    size_t qb = (size_t)head * HW + q0;
    #pragma unroll
    for (int i = 0; i < 8; i++) {
        int idx = tid + i * 256;
        int row = idx >> 4, j = idx & 15;
        float4 v = *(const float4*)(g_Q + (qb + row) * HD + 4 * j);
        *(float4*)(Qs + row * SP + 4 * j) =
            make_float4(f2tf(v.x * QSC), f2tf(v.y * QSC),
                        f2tf(v.z * QSC), f2tf(v.w * QSC));
        float4 w = *(const float4*)(g_relw + (qb + row) * HD + 4 * j);
        *(float4*)(Bws + row * SP + 4 * j) =
            make_float4(w.x * L2E, w.y * L2E, w.z * L2E, w.w * L2E);
    }

    // prefetch first tile's rel_h column (2 regs only)
    const float* rh0 = g_relh + (size_t)head * HD * HW + q0;
    float nbh0 = rh0[r0] * L2E, nbh1 = rh0[r1] * L2E;

    float O[8][4] = {};
    float m0r = -INFINITY, m1r = -INFINITY, l0 = 0.f, l1 = 0.f;

    for (int kt = 0; kt < HW / 64; kt++) {
        __syncthreads();  // previous tile's readers done
        size_t kb = (size_t)head * HW + kt * 64;
        #pragma unroll
        for (int i = 0; i < 4; i++) {                 // K: coalesced copy
            int idx = tid + i * 256;
            *(float4*)(Ks + (idx >> 4) * SP + 4 * (idx & 15)) =
                *(const float4*)(g_K + (kb + (idx >> 4)) * HD + 4 * (idx & 15));
        }
        #pragma unroll
        for (int i = 0; i < 4; i++) {                 // V: transpose-scatter
            int idx = tid + i * 256;
            int key = idx & 63, j = idx >> 6;
            float4 v = *(const float4*)(g_V + (kb + key) * HD + 4 * j);
            Vt[(4 * j + 0) * SP + key] = v.x;
            Vt[(4 * j + 1) * SP + key] = v.y;
            Vt[(4 * j + 2) * SP + key] = v.z;
            Vt[(4 * j + 3) * SP + key] = v.w;
        }
        float bh0 = nbh0, bh1 = nbh1;
        __syncthreads();

        if (kt + 1 < HW / 64) {                       // prefetch next bias col
            const float* rh = g_relh + ((size_t)head * HD + kt + 1) * HW + q0;
            nbh0 = rh[r0] * L2E; nbh1 = rh[r1] * L2E;
        }

        // ---- S = (Q*0.125*log2e) @ K^T + bias*log2e ----
        float S[8][4];
        #pragma unroll
        for (int n = 0; n < 8; n++) {
            int col = 8 * n + 2 * c4;
            float2 w0 = *(const float2*)(Bws + r0 * SP + col);
            float2 w1 = *(const float2*)(Bws + r1 * SP + col);
            S[n][0] = bh0 + w0.x; S[n][1] = bh0 + w0.y;
            S[n][2] = bh1 + w1.x; S[n][3] = bh1 + w1.y;
        }
        #pragma unroll
        for (int s = 0; s < 8; s++) {
            int kb8 = 8 * s + 2 * c4;
            float2 a0 = *(const float2*)(Qs + r0 * SP + kb8);
            float2 a1 = *(const float2*)(Qs + r1 * SP + kb8);
            #pragma unroll
            for (int n = 0; n < 8; n++) {
                float2 b = *(const float2*)(Ks + (8 * n + g) * SP + kb8);
                mma8(S[n], FU(a0.x), FU(a1.x), FU(a0.y), FU(a1.y),
                     FU(b.x), FU(b.y));
            }
        }

        // ---- online softmax in exp2 domain (rows private to quad) ----
        float mx0 = -INFINITY, mx1 = -INFINITY;
        #pragma unroll
        for (int n = 0; n < 8; n++) {
            mx0 = fmaxf(mx0, fmaxf(S[n][0], S[n][1]));
            mx1 = fmaxf(mx1, fmaxf(S[n][2], S[n][3]));
        }
        mx0 = fmaxf(mx0, __shfl_xor_sync(0xffffffffu, mx0, 1));
        mx0 = fmaxf(mx0, __shfl_xor_sync(0xffffffffu, mx0, 2));
        mx1 = fmaxf(mx1, __shfl_xor_sync(0xffffffffu, mx1, 1));
        mx1 = fmaxf(mx1, __shfl_xor_sync(0xffffffffu, mx1, 2));
        float nm0 = fmaxf(m0r, mx0), nm1 = fmaxf(m1r, mx1);
        float al0 = ex2f(m0r - nm0), al1 = ex2f(m1r - nm1);
        m0r = nm0; m1r = nm1;
        float s0 = 0.f, s1 = 0.f;
        #pragma unroll
        for (int n = 0; n < 8; n++) {
            float p00 = f2tf(ex2f(S[n][0] - nm0));
            float p01 = f2tf(ex2f(S[n][1] - nm0));
            float p10 = f2tf(ex2f(S[n][2] - nm1));
            float p11 = f2tf(ex2f(S[n][3] - nm1));
            s0 += p00 + p01; s1 += p10 + p11;
            S[n][0] = p00; S[n][1] = p01; S[n][2] = p10; S[n][3] = p11;
            O[n][0] *= al0; O[n][1] *= al0; O[n][2] *= al1; O[n][3] *= al1;
        }
        s0 += __shfl_xor_sync(0xffffffffu, s0, 1);
        s0 += __shfl_xor_sync(0xffffffffu, s0, 2);
        s1 += __shfl_xor_sync(0xffffffffu, s1, 1);
        s1 += __shfl_xor_sync(0xffffffffu, s1, 2);
        l0 = l0 * al0 + s0;
        l1 = l1 * al1 + s1;

        // ---- O += P @ V : A-frags directly from S registers ----
        #pragma unroll
        for (int s = 0; s < 8; s++) {
            uint32_t a0 = FU(S[s][0]), a1 = FU(S[s][2]);
            uint32_t a2 = FU(S[s][1]), a3 = FU(S[s][3]);
            int kb8 = 8 * s + 2 * c4;
            #pragma unroll
            for (int n = 0; n < 8; n++) {
                float2 b = *(const float2*)(Vt + (8 * n + g) * SP + kb8);
                mma8(O[n], a0, a1, a2, a3, FU(b.x), FU(b.y));
            }
        }
    }

    float inv0 = 1.0f / l0, inv1 = 1.0f / l1;
    #pragma unroll
    for (int n = 0; n < 8; n++) {
        int d = 8 * n + 2 * c4;
        *(float2*)(g_att + (size_t)(q0 + r0) * CC + head * HD + d) =
            make_float2(O[n][0] * inv0, O[n][1] * inv0);
        *(float2*)(g_att + (size_t)(q0 + r1) * CC + head * HD + d) =
            make_float2(O[n][2] * inv1, O[n][3] * inv1);
    }
}

// ---------------- launch -----------------------------------------------------
extern "C" void kernel_launch(void* const* d_in, const int* in_sizes, int n_in,
                              void* d_out, int out_size)
{
    const float* hs  = (const float*)d_in[0];
    const float* w_q = (const float*)d_in[1];
    const float* b_q = (const float*)d_in[2];
    const float* w_k = (const float*)d_in[3];
    const float* b_k = (const float*)d_in[4];
    const float* w_v = (const float*)d_in[5];
    const float* b_v = (const float*)d_in[6];
    const float* w_o = (const float*)d_in[7];
    const float* b_o = (const float*)d_in[8];
    const float* rph = (const float*)d_in[9];
    const float* rpw = (const float*)d_in[10];
    float* out = (float*)d_out;

    int proj_smem = (128 * SP + 64 * SP) * (int)sizeof(float);           // 55296 B
    int att_smem  = (2 * 128 * SP + 2 * 64 * SP) * (int)sizeof(float);   // 110592 B

    cudaFuncSetAttribute(projmma_kernel<0>, cudaFuncAttributeMaxDynamicSharedMemorySize, proj_smem);
    cudaFuncSetAttribute(projmma_kernel<1>, cudaFuncAttributeMaxDynamicSharedMemorySize, proj_smem);
    cudaFuncSetAttribute(projmma_kernel<2>, cudaFuncAttributeMaxDynamicSharedMemorySize, proj_smem);
    cudaFuncSetAttribute(projmma_kernel<3>, cudaFuncAttributeMaxDynamicSharedMemorySize, proj_smem);
    cudaFuncSetAttribute(attnmma_kernel, cudaFuncAttributeMaxDynamicSharedMemorySize, att_smem);

    dim3 gproj(CC / 64, HW / 128);  // (12, 32)
    projmma_kernel<0><<<gproj, 256, proj_smem>>>(hs, w_q, b_q, nullptr);
    projmma_kernel<1><<<gproj, 256, proj_smem>>>(hs, w_k, b_k, nullptr);
    projmma_kernel<2><<<gproj, 256, proj_smem>>>(hs, w_v, b_v, nullptr);

    relpos_kernel<<<dim3(64, NHEADS, 2), 256>>>(rph, rpw);

    attnmma_kernel<<<dim3(HW / 128, NHEADS), 256, att_smem>>>();

    projmma_kernel<3><<<gproj, 256, proj_smem>>>(nullptr, w_o, b_o, out);
}

// round 11
// speedup vs baseline: 2.2382x; 1.5844x over previous
#include <cuda_runtime.h>
#include <cuda_fp16.h>
#include <math.h>
#include <stdint.h>

#define HW 4096
#define CC 768
#define NHEADS 12
#define HD 64
#define SP 72   // smem row stride in HALVES: 36 words ≡ 4 (mod 32) -> LDS.32 conflict-free

// ---------------- scratch ----------------------------------------------------
// g_Q holds half(q * 0.125 * log2e); g_K/g_V half; g_relw half (bias*log2e).
__device__ __half g_Q[(size_t)NHEADS * HW * HD];
__device__ __half g_K[(size_t)NHEADS * HW * HD];
__device__ __half g_V[(size_t)NHEADS * HW * HD];
__device__ float  g_relh[(size_t)NHEADS * HD * HW];  // [head][kh][tok], *log2e
__device__ __half g_relw[(size_t)NHEADS * HW * HD];  // [head][tok][kw], *log2e
__device__ float  g_att[(size_t)HW * CC];

// ---------------- helpers ----------------------------------------------------
__device__ __forceinline__ float ex2f(float x) {
    float y;
    asm("ex2.approx.f32 %0, %1;" : "=f"(y) : "f"(x));
    return y;
}
__device__ __forceinline__ uint32_t pack_h2(float a, float b) {
    __half2 h = __floats2half2_rn(a, b);
    return *reinterpret_cast<uint32_t*>(&h);
}
__device__ __forceinline__ void mma16(float* c,
                                      uint32_t a0, uint32_t a1, uint32_t a2, uint32_t a3,
                                      uint32_t b0, uint32_t b1) {
    asm volatile(
        "mma.sync.aligned.m16n8k16.row.col.f32.f16.f16.f32 "
        "{%0,%1,%2,%3}, {%4,%5,%6,%7}, {%8,%9}, {%0,%1,%2,%3};\n"
        : "+f"(c[0]), "+f"(c[1]), "+f"(c[2]), "+f"(c[3])
        : "r"(a0), "r"(a1), "r"(a2), "r"(a3), "r"(b0), "r"(b1));
}
#define LDH2(p) (*reinterpret_cast<const uint32_t*>(p))

// ---------------- projection GEMM (fp16 mma): Y = X @ W^T + b ----------------
// tile 128(m) x 64(n); K=768 in 12 chunks of 64 (4 fp16 k-steps each).
// DEST 0: g_Q (scaled by 0.125*log2e), 1: g_K, 2: g_V, 3: fp32 Yout.
template <int DEST>
__global__ void __launch_bounds__(256, 2) projmma_kernel(
    const float* __restrict__ Xin, const float* __restrict__ W,
    const float* __restrict__ bias, float* __restrict__ Yout)
{
    extern __shared__ __half smh[];
    __half* Xs = smh;              // [128][SP]
    __half* Ws = smh + 128 * SP;   // [64][SP]
    const float* X = (DEST == 3) ? (const float*)g_att : Xin;

    int tid = threadIdx.x;
    int warp = tid >> 5, lane = tid & 31, g = lane >> 2, c4 = lane & 3;
    int m0 = blockIdx.y * 128, n0 = blockIdx.x * 64;
    int r0 = warp * 16 + g, r1 = r0 + 8;

    float acc[8][4] = {};

    for (int k0 = 0; k0 < CC; k0 += 64) {
        __syncthreads();
        #pragma unroll
        for (int i = 0; i < 8; i++) {                 // X: 128 rows x 16 float4
            int idx = tid + i * 256;
            int row = idx >> 4, j = idx & 15;
            float4 v = *(const float4*)(X + (size_t)(m0 + row) * CC + k0 + 4 * j);
            uint2 st;
            st.x = pack_h2(v.x, v.y); st.y = pack_h2(v.z, v.w);
            *(uint2*)(Xs + row * SP + 4 * j) = st;
        }
        #pragma unroll
        for (int i = 0; i < 4; i++) {                 // W: 64 rows x 16 float4
            int idx = tid + i * 256;
            int row = idx >> 4, j = idx & 15;
            float4 v = *(const float4*)(W + (size_t)(n0 + row) * CC + k0 + 4 * j);
            uint2 st;
            st.x = pack_h2(v.x, v.y); st.y = pack_h2(v.z, v.w);
            *(uint2*)(Ws + row * SP + 4 * j) = st;
        }
        __syncthreads();

        #pragma unroll
        for (int s = 0; s < 4; s++) {
            int kb = 16 * s + 2 * c4;
            uint32_t a0 = LDH2(Xs + r0 * SP + kb);
            uint32_t a1 = LDH2(Xs + r1 * SP + kb);
            uint32_t a2 = LDH2(Xs + r0 * SP + kb + 8);
            uint32_t a3 = LDH2(Xs + r1 * SP + kb + 8);
            #pragma unroll
            for (int n = 0; n < 8; n++) {
                uint32_t b0 = LDH2(Ws + (8 * n + g) * SP + kb);
                uint32_t b1 = LDH2(Ws + (8 * n + g) * SP + kb + 8);
                mma16(acc[n], a0, a1, a2, a3, b0, b1);
            }
        }
    }

    const float QSC = 0.125f * 1.44269504f;
    #pragma unroll
    for (int n = 0; n < 8; n++) {
        int col = n0 + 8 * n + 2 * c4;
        float b0v = bias[col], b1v = bias[col + 1];
        float x0 = acc[n][0] + b0v, x1 = acc[n][1] + b1v;
        float x2 = acc[n][2] + b0v, x3 = acc[n][3] + b1v;
        int mr0 = m0 + r0, mr1 = m0 + r1;
        if (DEST == 3) {
            *(float2*)(Yout + (size_t)mr0 * CC + col) = make_float2(x0, x1);
            *(float2*)(Yout + (size_t)mr1 * CC + col) = make_float2(x2, x3);
        } else {
            size_t o0 = ((size_t)(col >> 6) * HW + mr0) * HD + (col & 63);
            size_t o1 = ((size_t)(col >> 6) * HW + mr1) * HD + (col & 63);
            if (DEST == 0) {   // prescale Q for exp2-domain attention
                *(__half2*)(g_Q + o0) = __floats2half2_rn(x0 * QSC, x1 * QSC);
                *(__half2*)(g_Q + o1) = __floats2half2_rn(x2 * QSC, x3 * QSC);
            } else if (DEST == 1) {
                *(__half2*)(g_K + o0) = __floats2half2_rn(x0, x1);
                *(__half2*)(g_K + o1) = __floats2half2_rn(x2, x3);
            } else {
                *(__half2*)(g_V + o0) = __floats2half2_rn(x0, x1);
                *(__half2*)(g_V + o1) = __floats2half2_rn(x2, x3);
            }
        }
    }
}

// ---------------- decomposed rel-pos bias ------------------------------------
// Reads prescaled half Q; scales result by 8 => output = bias * log2e.
__global__ void __launch_bounds__(256) relpos_kernel(
    const float* __restrict__ rph, const float* __restrict__ rpw)
{
    __shared__ float Qs[64][65];
    __shared__ float Rs[64][65];
    int axis = blockIdx.z, head = blockIdx.y, a0 = blockIdx.x;
    int tid = threadIdx.x, tx = tid & 15, ty = tid >> 4;
    int lr = tid >> 2, lc = (tid & 3) * 4;

    int tok_l = (axis == 0) ? (a0 * 64 + lr) : (lr * 64 + a0);
    const float* rp = (axis == 0) ? rph : rpw;
    #pragma unroll
    for (int c0 = 0; c0 < 64; c0 += 16) {
        int c = lc + c0;
        uint2 qv = *(const uint2*)&g_Q[((size_t)head * HW + tok_l) * HD + c];
        __half2* hp = (__half2*)&qv;
        float2 f0 = __half22float2(hp[0]), f1 = __half22float2(hp[1]);
        Qs[lr][c + 0] = f0.x; Qs[lr][c + 1] = f0.y;
        Qs[lr][c + 2] = f1.x; Qs[lr][c + 3] = f1.y;
        float4 rv = *(const float4*)&rp[(size_t)(a0 - lr + 63) * HD + c];
        Rs[lr][c + 0] = rv.x; Rs[lr][c + 1] = rv.y;
        Rs[lr][c + 2] = rv.z; Rs[lr][c + 3] = rv.w;
    }
    __syncthreads();

    float acc[4][4] = {};
    #pragma unroll
    for (int d = 0; d < 64; d++) {
        float a[4], b[4];
        #pragma unroll
        for (int i = 0; i < 4; i++) a[i] = Qs[ty + i * 16][d];
        #pragma unroll
        for (int j = 0; j < 4; j++) b[j] = Rs[tx + j * 16][d];
        #pragma unroll
        for (int i = 0; i < 4; i++)
            #pragma unroll
            for (int j = 0; j < 4; j++)
                acc[i][j] = fmaf(a[i], b[j], acc[i][j]);
    }

    #pragma unroll
    for (int i = 0; i < 4; i++) {
        int r = ty + i * 16;
        int tok = (axis == 0) ? (a0 * 64 + r) : (r * 64 + a0);
        #pragma unroll
        for (int j = 0; j < 4; j++) {
            int k = tx + j * 16;
            float v = acc[i][j] * 8.0f;   // undo 0.125 prescale -> bias*log2e
            if (axis == 0)
                g_relh[((size_t)head * HD + k) * HW + tok] = v;
            else
                g_relw[((size_t)head * HW + tok) * HD + k] = __float2half(v);
        }
    }
}

// ---------------- flash attention, fp16 mma, no-max softmax ------------------
// q-tile 128, key-tile 64. Scores bounded -> plain ex2, O accumulates in mma
// regs across all tiles (no rescale). Register-P via half2 packing.
// smem = (128+128+64+64)*SP halves = 55296 B -> 2 CTAs/SM.
__global__ void __launch_bounds__(256, 2) attnmma_kernel()
{
    extern __shared__ __half smh[];
    __half* Qs  = smh;                  // [128][SP] prescaled q*0.125*log2e
    __half* Bws = Qs + 128 * SP;        // [128][SP] rel_w bias*log2e
    __half* Ks  = Bws + 128 * SP;       // [64][SP]
    __half* Vt  = Ks + 64 * SP;         // [64][SP] transposed [d][key]

    int tid = threadIdx.x;
    int warp = tid >> 5, lane = tid & 31, g = lane >> 2, c4 = lane & 3;
    int head = blockIdx.y, q0 = blockIdx.x * 128;
    int r0 = warp * 16 + g, r1 = r0 + 8;

    size_t qb = (size_t)head * HW + q0;
    #pragma unroll
    for (int i = 0; i < 4; i++) {       // Q + Bw: 128 rows x 8 uint4 each
        int idx = tid + i * 256;
        int row = idx >> 3, j = idx & 7;
        *(uint4*)(Qs + row * SP + 8 * j) =
            *(const uint4*)(g_Q + (qb + row) * HD + 8 * j);
        *(uint4*)(Bws + row * SP + 8 * j) =
            *(const uint4*)(g_relw + (qb + row) * HD + 8 * j);
    }

    const float* rh0 = g_relh + (size_t)head * HD * HW + q0;
    float nbh0 = rh0[r0], nbh1 = rh0[r1];

    float O[8][4] = {};
    float l0 = 0.f, l1 = 0.f;

    for (int kt = 0; kt < HW / 64; kt++) {
        __syncthreads();  // previous tile's readers done
        size_t kb = (size_t)head * HW + kt * 64;
        #pragma unroll
        for (int i = 0; i < 2; i++) {                 // K: 64 rows x 8 uint4
            int idx = tid + i * 256;
            int row = idx >> 3, j = idx & 7;
            *(uint4*)(Ks + row * SP + 8 * j) =
                *(const uint4*)(g_K + (kb + row) * HD + 8 * j);
        }
        #pragma unroll
        for (int i = 0; i < 2; i++) {                 // V: transpose-scatter
            int idx = tid + i * 256;
            int key = idx & 63, jj = idx >> 6;        // d = 8jj..8jj+7
            uint4 v = *(const uint4*)(g_V + (kb + key) * HD + 8 * jj);
            __half2* hp = (__half2*)&v;
            #pragma unroll
            for (int t = 0; t < 4; t++) {
                Vt[(8 * jj + 2 * t + 0) * SP + key] = __low2half(hp[t]);
                Vt[(8 * jj + 2 * t + 1) * SP + key] = __high2half(hp[t]);
            }
        }
        float bh0 = nbh0, bh1 = nbh1;
        __syncthreads();

        if (kt + 1 < HW / 64) {
            const float* rh = g_relh + ((size_t)head * HD + kt + 1) * HW + q0;
            nbh0 = rh[r0]; nbh1 = rh[r1];
        }

        // ---- S = bias; S += Qs @ K^T (exp2 domain) ----
        float S[8][4];
        #pragma unroll
        for (int n = 0; n < 8; n++) {
            int col = 8 * n + 2 * c4;
            float2 w0 = __half22float2(*(const __half2*)(Bws + r0 * SP + col));
            float2 w1 = __half22float2(*(const __half2*)(Bws + r1 * SP + col));
            S[n][0] = bh0 + w0.x; S[n][1] = bh0 + w0.y;
            S[n][2] = bh1 + w1.x; S[n][3] = bh1 + w1.y;
        }
        #pragma unroll
        for (int s = 0; s < 4; s++) {
            int kb16 = 16 * s + 2 * c4;
            uint32_t a0 = LDH2(Qs + r0 * SP + kb16);
            uint32_t a1 = LDH2(Qs + r1 * SP + kb16);
            uint32_t a2 = LDH2(Qs + r0 * SP + kb16 + 8);
            uint32_t a3 = LDH2(Qs + r1 * SP + kb16 + 8);
            #pragma unroll
            for (int n = 0; n < 8; n++) {
                uint32_t b0 = LDH2(Ks + (8 * n + g) * SP + kb16);
                uint32_t b1 = LDH2(Ks + (8 * n + g) * SP + kb16 + 8);
                mma16(S[n], a0, a1, a2, a3, b0, b1);
            }
        }

        // ---- softmax without max: p = ex2(s), pack to half2 ----
        uint32_t hr0[8], hr1[8];
        float s0 = 0.f, s1 = 0.f;
        #pragma unroll
        for (int n = 0; n < 8; n++) {
            float p00 = ex2f(S[n][0]), p01 = ex2f(S[n][1]);
            float p10 = ex2f(S[n][2]), p11 = ex2f(S[n][3]);
            s0 += p00 + p01; s1 += p10 + p11;
            hr0[n] = pack_h2(p00, p01);
            hr1[n] = pack_h2(p10, p11);
        }
        s0 += __shfl_xor_sync(0xffffffffu, s0, 1);
        s0 += __shfl_xor_sync(0xffffffffu, s0, 2);
        s1 += __shfl_xor_sync(0xffffffffu, s1, 1);
        s1 += __shfl_xor_sync(0xffffffffu, s1, 2);
        l0 += s0; l1 += s1;

        // ---- O += P @ V : A-frags from packed registers ----
        #pragma unroll
        for (int s = 0; s < 4; s++) {
            uint32_t a0 = hr0[2 * s], a1 = hr1[2 * s];
            uint32_t a2 = hr0[2 * s + 1], a3 = hr1[2 * s + 1];
            int kb16 = 16 * s + 2 * c4;
            #pragma unroll
            for (int n = 0; n < 8; n++) {
                uint32_t b0 = LDH2(Vt + (8 * n + g) * SP + kb16);
                uint32_t b1 = LDH2(Vt + (8 * n + g) * SP + kb16 + 8);
                mma16(O[n], a0, a1, a2, a3, b0, b1);
            }
        }
    }

    float inv0 = 1.0f / l0, inv1 = 1.0f / l1;
    #pragma unroll
    for (int n = 0; n < 8; n++) {
        int d = 8 * n + 2 * c4;
        *(float2*)(g_att + (size_t)(q0 + r0) * CC + head * HD + d) =
            make_float2(O[n][0] * inv0, O[n][1] * inv0);
        *(float2*)(g_att + (size_t)(q0 + r1) * CC + head * HD + d) =
            make_float2(O[n][2] * inv1, O[n][3] * inv1);
    }
}

// ---------------- launch -----------------------------------------------------
extern "C" void kernel_launch(void* const* d_in, const int* in_sizes, int n_in,
                              void* d_out, int out_size)
{
    const float* hs  = (const float*)d_in[0];
    const float* w_q = (const float*)d_in[1];
    const float* b_q = (const float*)d_in[2];
    const float* w_k = (const float*)d_in[3];
    const float* b_k = (const float*)d_in[4];
    const float* w_v = (const float*)d_in[5];
    const float* b_v = (const float*)d_in[6];
    const float* w_o = (const float*)d_in[7];
    const float* b_o = (const float*)d_in[8];
    const float* rph = (const float*)d_in[9];
    const float* rpw = (const float*)d_in[10];
    float* out = (float*)d_out;

    int proj_smem = (128 * SP + 64 * SP) * (int)sizeof(__half);            // 27648 B
    int att_smem  = (2 * 128 * SP + 2 * 64 * SP) * (int)sizeof(__half);    // 55296 B

    cudaFuncSetAttribute(projmma_kernel<0>, cudaFuncAttributeMaxDynamicSharedMemorySize, proj_smem);
    cudaFuncSetAttribute(projmma_kernel<1>, cudaFuncAttributeMaxDynamicSharedMemorySize, proj_smem);
    cudaFuncSetAttribute(projmma_kernel<2>, cudaFuncAttributeMaxDynamicSharedMemorySize, proj_smem);
    cudaFuncSetAttribute(projmma_kernel<3>, cudaFuncAttributeMaxDynamicSharedMemorySize, proj_smem);
    cudaFuncSetAttribute(attnmma_kernel, cudaFuncAttributeMaxDynamicSharedMemorySize, att_smem);

    dim3 gproj(CC / 64, HW / 128);  // (12, 32)
    projmma_kernel<0><<<gproj, 256, proj_smem>>>(hs, w_q, b_q, nullptr);
    projmma_kernel<1><<<gproj, 256, proj_smem>>>(hs, w_k, b_k, nullptr);
    projmma_kernel<2><<<gproj, 256, proj_smem>>>(hs, w_v, b_v, nullptr);

    relpos_kernel<<<dim3(64, NHEADS, 2), 256>>>(rph, rpw);

    attnmma_kernel<<<dim3(HW / 128, NHEADS), 256, att_smem>>>();

    projmma_kernel<3><<<gproj, 256, proj_smem>>>(nullptr, w_o, b_o, out);
}

// round 12
// speedup vs baseline: 2.6476x; 1.1829x over previous
#include <cuda_runtime.h>
#include <cuda_fp16.h>
#include <math.h>
#include <stdint.h>

#define HW 4096
#define CC 768
#define NHEADS 12
#define HD 64
#define SP 72   // smem stride in halves: conflict-free for LDS.32/64/128 patterns used

// ---------------- scratch ----------------------------------------------------
__device__ __half g_Xh[(size_t)HW * CC];            // hidden_states, half
__device__ __half g_Q[(size_t)NHEADS * HW * HD];    // q * 0.125 * log2e
__device__ __half g_K[(size_t)NHEADS * HW * HD];
__device__ __half g_V[(size_t)NHEADS * HW * HD];
__device__ float  g_relh[(size_t)NHEADS * HD * HW]; // [head][kh][tok], *log2e
__device__ __half g_relw[(size_t)NHEADS * HW * HD]; // [head][tok][kw], *log2e
__device__ __half g_att_h[(size_t)HW * CC];         // attention out, half

// ---------------- helpers ----------------------------------------------------
__device__ __forceinline__ float ex2f(float x) {
    float y;
    asm("ex2.approx.f32 %0, %1;" : "=f"(y) : "f"(x));
    return y;
}
__device__ __forceinline__ uint32_t pack_h2(float a, float b) {
    __half2 h = __floats2half2_rn(a, b);
    return *reinterpret_cast<uint32_t*>(&h);
}
__device__ __forceinline__ void mma16(float* c,
                                      uint32_t a0, uint32_t a1, uint32_t a2, uint32_t a3,
                                      uint32_t b0, uint32_t b1) {
    asm volatile(
        "mma.sync.aligned.m16n8k16.row.col.f32.f16.f16.f32 "
        "{%0,%1,%2,%3}, {%4,%5,%6,%7}, {%8,%9}, {%0,%1,%2,%3};\n"
        : "+f"(c[0]), "+f"(c[1]), "+f"(c[2]), "+f"(c[3])
        : "r"(a0), "r"(a1), "r"(a2), "r"(a3), "r"(b0), "r"(b1));
}
#define LDH2(p) (*reinterpret_cast<const uint32_t*>(p))

// ---------------- X fp32 -> half ---------------------------------------------
__global__ void __launch_bounds__(256) cvt_kernel(const float* __restrict__ hs)
{
    size_t i = ((size_t)blockIdx.x * 256 + threadIdx.x) * 4;
    float4 v = *(const float4*)(hs + i);
    uint2 st;
    st.x = pack_h2(v.x, v.y); st.y = pack_h2(v.z, v.w);
    *(uint2*)&g_Xh[i] = st;
}

// ---------------- fused QKV projection (fp16 mma, 256x64 tile) ---------------
// grid (12, 16, 3): x = n-block (dest head chunk), y = m-block, z = {Q,K,V}.
// 8 warps x 32 rows (2 m-tiles each) -> 2-way B reuse. acc[2][8][4].
__global__ void __launch_bounds__(256, 2) projqkv_kernel(
    const float* __restrict__ wq, const float* __restrict__ bq,
    const float* __restrict__ wk, const float* __restrict__ bk,
    const float* __restrict__ wv, const float* __restrict__ bv)
{
    extern __shared__ __half smh[];
    __half* Xs = smh;              // [256][SP]
    __half* Ws = smh + 256 * SP;   // [64][SP]

    int z = blockIdx.z;
    const float* W = (z == 0) ? wq : (z == 1) ? wk : wv;
    const float* B = (z == 0) ? bq : (z == 1) ? bk : bv;
    __half* dst = (z == 0) ? g_Q : (z == 1) ? g_K : g_V;
    const float scale = (z == 0) ? 0.125f * 1.44269504f : 1.0f;

    int tid = threadIdx.x;
    int warp = tid >> 5, lane = tid & 31, g = lane >> 2, c4 = lane & 3;
    int m0 = blockIdx.y * 256, n0 = blockIdx.x * 64;
    int rb = warp << 5;

    float acc[2][8][4] = {};

    for (int k0 = 0; k0 < CC; k0 += 64) {
        __syncthreads();
        #pragma unroll
        for (int i = 0; i < 8; i++) {                 // X: 256 rows x 8 uint4
            int idx = tid + i * 256;
            int row = idx >> 3, j = idx & 7;
            *(uint4*)(Xs + row * SP + 8 * j) =
                *(const uint4*)(g_Xh + (size_t)(m0 + row) * CC + k0 + 8 * j);
        }
        #pragma unroll
        for (int i = 0; i < 4; i++) {                 // W: 64 rows x 16 float4
            int idx = tid + i * 256;
            int row = idx >> 4, j = idx & 15;
            float4 v = *(const float4*)(W + (size_t)(n0 + row) * CC + k0 + 4 * j);
            uint2 st;
            st.x = pack_h2(v.x, v.y); st.y = pack_h2(v.z, v.w);
            *(uint2*)(Ws + row * SP + 4 * j) = st;
        }
        __syncthreads();

        #pragma unroll
        for (int s = 0; s < 4; s++) {
            int kb = 16 * s + 2 * c4;
            uint32_t A[2][4];
            #pragma unroll
            for (int m = 0; m < 2; m++) {
                int rr = rb + 16 * m + g;
                A[m][0] = LDH2(Xs + rr * SP + kb);
                A[m][1] = LDH2(Xs + (rr + 8) * SP + kb);
                A[m][2] = LDH2(Xs + rr * SP + kb + 8);
                A[m][3] = LDH2(Xs + (rr + 8) * SP + kb + 8);
            }
            #pragma unroll
            for (int n = 0; n < 8; n++) {
                uint32_t b0 = LDH2(Ws + (8 * n + g) * SP + kb);
                uint32_t b1 = LDH2(Ws + (8 * n + g) * SP + kb + 8);
                mma16(acc[0][n], A[0][0], A[0][1], A[0][2], A[0][3], b0, b1);
                mma16(acc[1][n], A[1][0], A[1][1], A[1][2], A[1][3], b0, b1);
            }
        }
    }

    #pragma unroll
    for (int n = 0; n < 8; n++) {
        int col = n0 + 8 * n + 2 * c4;
        float b0v = B[col], b1v = B[col + 1];
        size_t base = (size_t)(col >> 6) * HW;
        #pragma unroll
        for (int m = 0; m < 2; m++) {
            int mr0 = m0 + rb + 16 * m + g, mr1 = mr0 + 8;
            *(__half2*)(dst + (base + mr0) * HD + (col & 63)) =
                __floats2half2_rn((acc[m][n][0] + b0v) * scale,
                                  (acc[m][n][1] + b1v) * scale);
            *(__half2*)(dst + (base + mr1) * HD + (col & 63)) =
                __floats2half2_rn((acc[m][n][2] + b0v) * scale,
                                  (acc[m][n][3] + b1v) * scale);
        }
    }
}

// ---------------- output projection (fp16 mma, 256x64 tile, fp32 out) --------
__global__ void __launch_bounds__(256, 2) projout_kernel(
    const float* __restrict__ W, const float* __restrict__ B,
    float* __restrict__ Yout)
{
    extern __shared__ __half smh[];
    __half* Xs = smh;
    __half* Ws = smh + 256 * SP;

    int tid = threadIdx.x;
    int warp = tid >> 5, lane = tid & 31, g = lane >> 2, c4 = lane & 3;
    int m0 = blockIdx.y * 256, n0 = blockIdx.x * 64;
    int rb = warp << 5;

    float acc[2][8][4] = {};

    for (int k0 = 0; k0 < CC; k0 += 64) {
        __syncthreads();
        #pragma unroll
        for (int i = 0; i < 8; i++) {
            int idx = tid + i * 256;
            int row = idx >> 3, j = idx & 7;
            *(uint4*)(Xs + row * SP + 8 * j) =
                *(const uint4*)(g_att_h + (size_t)(m0 + row) * CC + k0 + 8 * j);
        }
        #pragma unroll
        for (int i = 0; i < 4; i++) {
            int idx = tid + i * 256;
            int row = idx >> 4, j = idx & 15;
            float4 v = *(const float4*)(W + (size_t)(n0 + row) * CC + k0 + 4 * j);
            uint2 st;
            st.x = pack_h2(v.x, v.y); st.y = pack_h2(v.z, v.w);
            *(uint2*)(Ws + row * SP + 4 * j) = st;
        }
        __syncthreads();

        #pragma unroll
        for (int s = 0; s < 4; s++) {
            int kb = 16 * s + 2 * c4;
            uint32_t A[2][4];
            #pragma unroll
            for (int m = 0; m < 2; m++) {
                int rr = rb + 16 * m + g;
                A[m][0] = LDH2(Xs + rr * SP + kb);
                A[m][1] = LDH2(Xs + (rr + 8) * SP + kb);
                A[m][2] = LDH2(Xs + rr * SP + kb + 8);
                A[m][3] = LDH2(Xs + (rr + 8) * SP + kb + 8);
            }
            #pragma unroll
            for (int n = 0; n < 8; n++) {
                uint32_t b0 = LDH2(Ws + (8 * n + g) * SP + kb);
                uint32_t b1 = LDH2(Ws + (8 * n + g) * SP + kb + 8);
                mma16(acc[0][n], A[0][0], A[0][1], A[0][2], A[0][3], b0, b1);
                mma16(acc[1][n], A[1][0], A[1][1], A[1][2], A[1][3], b0, b1);
            }
        }
    }

    #pragma unroll
    for (int n = 0; n < 8; n++) {
        int col = n0 + 8 * n + 2 * c4;
        float b0v = B[col], b1v = B[col + 1];
        #pragma unroll
        for (int m = 0; m < 2; m++) {
            int mr0 = m0 + rb + 16 * m + g, mr1 = mr0 + 8;
            *(float2*)(Yout + (size_t)mr0 * CC + col) =
                make_float2(acc[m][n][0] + b0v, acc[m][n][1] + b1v);
            *(float2*)(Yout + (size_t)mr1 * CC + col) =
                make_float2(acc[m][n][2] + b0v, acc[m][n][3] + b1v);
        }
    }
}

// ---------------- decomposed rel-pos bias (fp16 mma) -------------------------
// grid (64, 12, 2), block 128 (4 warps x 16 rows). Out = (Qs @ R^T) * 8
// (Q prescaled by 0.125*log2e -> result = bias*log2e).
__global__ void __launch_bounds__(128) relpos_kernel(
    const float* __restrict__ rph, const float* __restrict__ rpw)
{
    __shared__ __half Qs[64 * SP];
    __shared__ __half Rs[64 * SP];
    int axis = blockIdx.z, head = blockIdx.y, a0 = blockIdx.x;
    int tid = threadIdx.x;
    int warp = tid >> 5, lane = tid & 31, g = lane >> 2, c4 = lane & 3;

    const float* rp = (axis == 0) ? rph : rpw;
    #pragma unroll
    for (int i = 0; i < 4; i++) {       // Q: 64 rows x 8 uint4
        int idx = tid + i * 128;
        int row = idx >> 3, j = idx & 7;
        int tok = (axis == 0) ? (a0 * 64 + row) : (row * 64 + a0);
        *(uint4*)(Qs + row * SP + 8 * j) =
            *(const uint4*)(g_Q + ((size_t)head * HW + tok) * HD + 8 * j);
    }
    #pragma unroll
    for (int i = 0; i < 8; i++) {       // R: 64 rows x 16 float4 -> half
        int idx = tid + i * 128;
        int row = idx >> 4, j = idx & 15;
        float4 v = *(const float4*)(rp + (size_t)(a0 - row + 63) * HD + 4 * j);
        uint2 st;
        st.x = pack_h2(v.x, v.y); st.y = pack_h2(v.z, v.w);
        *(uint2*)(Rs + row * SP + 4 * j) = st;
    }
    __syncthreads();

    int r0 = warp * 16 + g, r1 = r0 + 8;
    float acc[8][4] = {};
    #pragma unroll
    for (int s = 0; s < 4; s++) {
        int kb = 16 * s + 2 * c4;
        uint32_t a0r = LDH2(Qs + r0 * SP + kb);
        uint32_t a1r = LDH2(Qs + r1 * SP + kb);
        uint32_t a2r = LDH2(Qs + r0 * SP + kb + 8);
        uint32_t a3r = LDH2(Qs + r1 * SP + kb + 8);
        #pragma unroll
        for (int n = 0; n < 8; n++) {
            uint32_t b0 = LDH2(Rs + (8 * n + g) * SP + kb);
            uint32_t b1 = LDH2(Rs + (8 * n + g) * SP + kb + 8);
            mma16(acc[n], a0r, a1r, a2r, a3r, b0, b1);
        }
    }

    #pragma unroll
    for (int n = 0; n < 8; n++) {
        int k = 8 * n + 2 * c4;
        float v00 = acc[n][0] * 8.f, v01 = acc[n][1] * 8.f;
        float v10 = acc[n][2] * 8.f, v11 = acc[n][3] * 8.f;
        if (axis == 0) {
            int t0 = a0 * 64 + r0, t1 = a0 * 64 + r1;
            g_relh[((size_t)head * HD + k) * HW + t0] = v00;
            g_relh[((size_t)head * HD + k + 1) * HW + t0] = v01;
            g_relh[((size_t)head * HD + k) * HW + t1] = v10;
            g_relh[((size_t)head * HD + k + 1) * HW + t1] = v11;
        } else {
            int t0 = r0 * 64 + a0, t1 = r1 * 64 + a0;
            *(__half2*)(g_relw + ((size_t)head * HW + t0) * HD + k) =
                __floats2half2_rn(v00, v01);
            *(__half2*)(g_relw + ((size_t)head * HW + t1) * HD + k) =
                __floats2half2_rn(v10, v11);
        }
    }
}

// ---------------- flash attention (unchanged core, half output) --------------
__global__ void __launch_bounds__(256, 2) attnmma_kernel()
{
    extern __shared__ __half smh[];
    __half* Qs  = smh;                  // [128][SP]
    __half* Bws = Qs + 128 * SP;        // [128][SP]
    __half* Ks  = Bws + 128 * SP;       // [64][SP]
    __half* Vt  = Ks + 64 * SP;         // [64][SP] transposed [d][key]

    int tid = threadIdx.x;
    int warp = tid >> 5, lane = tid & 31, g = lane >> 2, c4 = lane & 3;
    int head = blockIdx.y, q0 = blockIdx.x * 128;
    int r0 = warp * 16 + g, r1 = r0 + 8;

    size_t qb = (size_t)head * HW + q0;
    #pragma unroll
    for (int i = 0; i < 4; i++) {
        int idx = tid + i * 256;
        int row = idx >> 3, j = idx & 7;
        *(uint4*)(Qs + row * SP + 8 * j) =
            *(const uint4*)(g_Q + (qb + row) * HD + 8 * j);
        *(uint4*)(Bws + row * SP + 8 * j) =
            *(const uint4*)(g_relw + (qb + row) * HD + 8 * j);
    }

    const float* rh0 = g_relh + (size_t)head * HD * HW + q0;
    float nbh0 = rh0[r0], nbh1 = rh0[r1];

    float O[8][4] = {};
    float l0 = 0.f, l1 = 0.f;

    for (int kt = 0; kt < HW / 64; kt++) {
        __syncthreads();
        size_t kb = (size_t)head * HW + kt * 64;
        #pragma unroll
        for (int i = 0; i < 2; i++) {
            int idx = tid + i * 256;
            int row = idx >> 3, j = idx & 7;
            *(uint4*)(Ks + row * SP + 8 * j) =
                *(const uint4*)(g_K + (kb + row) * HD + 8 * j);
        }
        #pragma unroll
        for (int i = 0; i < 2; i++) {
            int idx = tid + i * 256;
            int key = idx & 63, jj = idx >> 6;
            uint4 v = *(const uint4*)(g_V + (kb + key) * HD + 8 * jj);
            __half2* hp = (__half2*)&v;
            #pragma unroll
            for (int t = 0; t < 4; t++) {
                Vt[(8 * jj + 2 * t + 0) * SP + key] = __low2half(hp[t]);
                Vt[(8 * jj + 2 * t + 1) * SP + key] = __high2half(hp[t]);
            }
        }
        float bh0 = nbh0, bh1 = nbh1;
        __syncthreads();

        if (kt + 1 < HW / 64) {
            const float* rh = g_relh + ((size_t)head * HD + kt + 1) * HW + q0;
            nbh0 = rh[r0]; nbh1 = rh[r1];
        }

        float S[8][4];
        #pragma unroll
        for (int n = 0; n < 8; n++) {
            int col = 8 * n + 2 * c4;
            float2 w0 = __half22float2(*(const __half2*)(Bws + r0 * SP + col));
            float2 w1 = __half22float2(*(const __half2*)(Bws + r1 * SP + col));
            S[n][0] = bh0 + w0.x; S[n][1] = bh0 + w0.y;
            S[n][2] = bh1 + w1.x; S[n][3] = bh1 + w1.y;
        }
        #pragma unroll
        for (int s = 0; s < 4; s++) {
            int kb16 = 16 * s + 2 * c4;
            uint32_t a0 = LDH2(Qs + r0 * SP + kb16);
            uint32_t a1 = LDH2(Qs + r1 * SP + kb16);
            uint32_t a2 = LDH2(Qs + r0 * SP + kb16 + 8);
            uint32_t a3 = LDH2(Qs + r1 * SP + kb16 + 8);
            #pragma unroll
            for (int n = 0; n < 8; n++) {
                uint32_t b0 = LDH2(Ks + (8 * n + g) * SP + kb16);
                uint32_t b1 = LDH2(Ks + (8 * n + g) * SP + kb16 + 8);
                mma16(S[n], a0, a1, a2, a3, b0, b1);
            }
        }

        uint32_t hr0[8], hr1[8];
        float s0 = 0.f, s1 = 0.f;
        #pragma unroll
        for (int n = 0; n < 8; n++) {
            float p00 = ex2f(S[n][0]), p01 = ex2f(S[n][1]);
            float p10 = ex2f(S[n][2]), p11 = ex2f(S[n][3]);
            s0 += p00 + p01; s1 += p10 + p11;
            hr0[n] = pack_h2(p00, p01);
            hr1[n] = pack_h2(p10, p11);
        }
        s0 += __shfl_xor_sync(0xffffffffu, s0, 1);
        s0 += __shfl_xor_sync(0xffffffffu, s0, 2);
        s1 += __shfl_xor_sync(0xffffffffu, s1, 1);
        s1 += __shfl_xor_sync(0xffffffffu, s1, 2);
        l0 += s0; l1 += s1;

        #pragma unroll
        for (int s = 0; s < 4; s++) {
            uint32_t a0 = hr0[2 * s], a1 = hr1[2 * s];
            uint32_t a2 = hr0[2 * s + 1], a3 = hr1[2 * s + 1];
            int kb16 = 16 * s + 2 * c4;
            #pragma unroll
            for (int n = 0; n < 8; n++) {
                uint32_t b0 = LDH2(Vt + (8 * n + g) * SP + kb16);
                uint32_t b1 = LDH2(Vt + (8 * n + g) * SP + kb16 + 8);
                mma16(O[n], a0, a1, a2, a3, b0, b1);
            }
        }
    }

    float inv0 = 1.0f / l0, inv1 = 1.0f / l1;
    #pragma unroll
    for (int n = 0; n < 8; n++) {
        int d = 8 * n + 2 * c4;
        *(__half2*)(g_att_h + (size_t)(q0 + r0) * CC + head * HD + d) =
            __floats2half2_rn(O[n][0] * inv0, O[n][1] * inv0);
        *(__half2*)(g_att_h + (size_t)(q0 + r1) * CC + head * HD + d) =
            __floats2half2_rn(O[n][2] * inv1, O[n][3] * inv1);
    }
}

// ---------------- launch -----------------------------------------------------
extern "C" void kernel_launch(void* const* d_in, const int* in_sizes, int n_in,
                              void* d_out, int out_size)
{
    const float* hs  = (const float*)d_in[0];
    const float* w_q = (const float*)d_in[1];
    const float* b_q = (const float*)d_in[2];
    const float* w_k = (const float*)d_in[3];
    const float* b_k = (const float*)d_in[4];
    const float* w_v = (const float*)d_in[5];
    const float* b_v = (const float*)d_in[6];
    const float* w_o = (const float*)d_in[7];
    const float* b_o = (const float*)d_in[8];
    const float* rph = (const float*)d_in[9];
    const float* rpw = (const float*)d_in[10];
    float* out = (float*)d_out;

    int proj_smem = (256 * SP + 64 * SP) * (int)sizeof(__half);           // 46080 B
    int att_smem  = (2 * 128 * SP + 2 * 64 * SP) * (int)sizeof(__half);   // 55296 B

    cudaFuncSetAttribute(projqkv_kernel, cudaFuncAttributeMaxDynamicSharedMemorySize, proj_smem);
    cudaFuncSetAttribute(projout_kernel, cudaFuncAttributeMaxDynamicSharedMemorySize, proj_smem);
    cudaFuncSetAttribute(attnmma_kernel, cudaFuncAttributeMaxDynamicSharedMemorySize, att_smem);

    cvt_kernel<<<HW * CC / 1024, 256>>>(hs);

    projqkv_kernel<<<dim3(CC / 64, HW / 256, 3), 256, proj_smem>>>(
        w_q, b_q, w_k, b_k, w_v, b_v);

    relpos_kernel<<<dim3(64, NHEADS, 2), 128>>>(rph, rpw);

    attnmma_kernel<<<dim3(HW / 128, NHEADS), 256, att_smem>>>();

    projout_kernel<<<dim3(CC / 64, HW / 256), 256, proj_smem>>>(w_o, b_o, out);
}

// round 13
// speedup vs baseline: 3.2401x; 1.2238x over previous
#include <cuda_runtime.h>
#include <cuda_fp16.h>
#include <math.h>
#include <stdint.h>

#define HW 4096
#define CC 768
#define NHEADS 12
#define HD 64
#define SP 72   // smem stride in halves; 144B rows -> ldmatrix conflict-free

// ---------------- scratch ----------------------------------------------------
__device__ __half g_Xh[(size_t)HW * CC];            // hidden_states, half
__device__ __half g_Q[(size_t)NHEADS * HW * HD];    // q * 0.125 * log2e
__device__ __half g_K[(size_t)NHEADS * HW * HD];
__device__ __half g_V[(size_t)NHEADS * HW * HD];
__device__ float  g_relh[(size_t)NHEADS * HD * HW]; // [head][kh][tok], *log2e
__device__ __half g_relw[(size_t)NHEADS * HW * HD]; // [head][tok][kw], *log2e
__device__ __half g_att_h[(size_t)HW * CC];         // attention out, half

// ---------------- helpers ----------------------------------------------------
__device__ __forceinline__ float ex2f(float x) {
    float y;
    asm("ex2.approx.f32 %0, %1;" : "=f"(y) : "f"(x));
    return y;
}
__device__ __forceinline__ uint32_t pack_h2(float a, float b) {
    __half2 h = __floats2half2_rn(a, b);
    return *reinterpret_cast<uint32_t*>(&h);
}
__device__ __forceinline__ uint32_t smem_u32(const void* p) {
    uint32_t a;
    asm("{ .reg .u64 t; cvta.to.shared.u64 t, %1; cvt.u32.u64 %0, t; }"
        : "=r"(a) : "l"(p));
    return a;
}
__device__ __forceinline__ void mma16(float* c,
                                      uint32_t a0, uint32_t a1, uint32_t a2, uint32_t a3,
                                      uint32_t b0, uint32_t b1) {
    asm volatile(
        "mma.sync.aligned.m16n8k16.row.col.f32.f16.f16.f32 "
        "{%0,%1,%2,%3}, {%4,%5,%6,%7}, {%8,%9}, {%0,%1,%2,%3};\n"
        : "+f"(c[0]), "+f"(c[1]), "+f"(c[2]), "+f"(c[3])
        : "r"(a0), "r"(a1), "r"(a2), "r"(a3), "r"(b0), "r"(b1));
}
__device__ __forceinline__ void ldsm4(uint32_t& r0, uint32_t& r1, uint32_t& r2,
                                      uint32_t& r3, uint32_t a) {
    asm volatile("ldmatrix.sync.aligned.m8n8.x4.shared.b16 {%0,%1,%2,%3}, [%4];"
                 : "=r"(r0), "=r"(r1), "=r"(r2), "=r"(r3) : "r"(a));
}
__device__ __forceinline__ void ldsm4t(uint32_t& r0, uint32_t& r1, uint32_t& r2,
                                       uint32_t& r3, uint32_t a) {
    asm volatile("ldmatrix.sync.aligned.m8n8.x4.trans.shared.b16 {%0,%1,%2,%3}, [%4];"
                 : "=r"(r0), "=r"(r1), "=r"(r2), "=r"(r3) : "r"(a));
}
#define LDH2(p) (*reinterpret_cast<const uint32_t*>(p))

// ---------------- X fp32 -> half ---------------------------------------------
__global__ void __launch_bounds__(256) cvt_kernel(const float* __restrict__ hs)
{
    size_t i = ((size_t)blockIdx.x * 256 + threadIdx.x) * 4;
    float4 v = *(const float4*)(hs + i);
    uint2 st;
    st.x = pack_h2(v.x, v.y); st.y = pack_h2(v.z, v.w);
    *(uint2*)&g_Xh[i] = st;
}

// ---------------- fused QKV projection (fp16 mma + ldmatrix) -----------------
// grid (12, 16, 3). 256x64 tile, 8 warps x 32 rows (2 m-tiles each).
__global__ void __launch_bounds__(256, 2) projqkv_kernel(
    const float* __restrict__ wq, const float* __restrict__ bq,
    const float* __restrict__ wk, const float* __restrict__ bk,
    const float* __restrict__ wv, const float* __restrict__ bv)
{
    extern __shared__ __half smh[];
    __half* Xs = smh;              // [256][SP]
    __half* Ws = smh + 256 * SP;   // [64][SP]

    int z = blockIdx.z;
    const float* W = (z == 0) ? wq : (z == 1) ? wk : wv;
    const float* B = (z == 0) ? bq : (z == 1) ? bk : bv;
    __half* dst = (z == 0) ? g_Q : (z == 1) ? g_K : g_V;
    const float scale = (z == 0) ? 0.125f * 1.44269504f : 1.0f;

    int tid = threadIdx.x;
    int warp = tid >> 5, lane = tid & 31, g = lane >> 2, c4 = lane & 3;
    int m0 = blockIdx.y * 256, n0 = blockIdx.x * 64;
    int rb = warp << 5;

    uint32_t sb = smem_u32(smh);
    uint32_t xa0 = sb + (uint32_t)((rb + (lane & 15)) * SP + ((lane & 16) >> 1)) * 2;
    uint32_t xa1 = xa0 + 16 * SP * 2;
    uint32_t wa = sb + (uint32_t)(256 * SP + ((lane & 7) + ((lane & 16) >> 1)) * SP
                                  + (lane & 8)) * 2;

    float acc[2][8][4] = {};

    for (int k0 = 0; k0 < CC; k0 += 64) {
        __syncthreads();
        #pragma unroll
        for (int i = 0; i < 8; i++) {                 // X: 256 rows x 8 uint4
            int idx = tid + i * 256;
            int row = idx >> 3, j = idx & 7;
            *(uint4*)(Xs + row * SP + 8 * j) =
                *(const uint4*)(g_Xh + (size_t)(m0 + row) * CC + k0 + 8 * j);
        }
        #pragma unroll
        for (int i = 0; i < 4; i++) {                 // W: 64 rows x 16 float4
            int idx = tid + i * 256;
            int row = idx >> 4, j = idx & 15;
            float4 v = *(const float4*)(W + (size_t)(n0 + row) * CC + k0 + 4 * j);
            uint2 st;
            st.x = pack_h2(v.x, v.y); st.y = pack_h2(v.z, v.w);
            *(uint2*)(Ws + row * SP + 4 * j) = st;
        }
        __syncthreads();

        #pragma unroll
        for (int s = 0; s < 4; s++) {
            uint32_t A0[4], A1[4];
            ldsm4(A0[0], A0[1], A0[2], A0[3], xa0 + 32 * s);
            ldsm4(A1[0], A1[1], A1[2], A1[3], xa1 + 32 * s);
            #pragma unroll
            for (int jp = 0; jp < 4; jp++) {
                uint32_t b0, b1, b2, b3;
                ldsm4(b0, b1, b2, b3, wa + jp * (32 * SP) + 32 * s);
                mma16(acc[0][2 * jp], A0[0], A0[1], A0[2], A0[3], b0, b1);
                mma16(acc[0][2 * jp + 1], A0[0], A0[1], A0[2], A0[3], b2, b3);
                mma16(acc[1][2 * jp], A1[0], A1[1], A1[2], A1[3], b0, b1);
                mma16(acc[1][2 * jp + 1], A1[0], A1[1], A1[2], A1[3], b2, b3);
            }
        }
    }

    #pragma unroll
    for (int n = 0; n < 8; n++) {
        int col = n0 + 8 * n + 2 * c4;
        float b0v = B[col], b1v = B[col + 1];
        size_t base = (size_t)(col >> 6) * HW;
        #pragma unroll
        for (int m = 0; m < 2; m++) {
            int mr0 = m0 + rb + 16 * m + g, mr1 = mr0 + 8;
            *(__half2*)(dst + (base + mr0) * HD + (col & 63)) =
                __floats2half2_rn((acc[m][n][0] + b0v) * scale,
                                  (acc[m][n][1] + b1v) * scale);
            *(__half2*)(dst + (base + mr1) * HD + (col & 63)) =
                __floats2half2_rn((acc[m][n][2] + b0v) * scale,
                                  (acc[m][n][3] + b1v) * scale);
        }
    }
}

// ---------------- output projection (fp16 mma + ldmatrix, fp32 out) ----------
__global__ void __launch_bounds__(256, 2) projout_kernel(
    const float* __restrict__ W, const float* __restrict__ B,
    float* __restrict__ Yout)
{
    extern __shared__ __half smh[];
    __half* Xs = smh;
    __half* Ws = smh + 256 * SP;

    int tid = threadIdx.x;
    int warp = tid >> 5, lane = tid & 31, g = lane >> 2, c4 = lane & 3;
    int m0 = blockIdx.y * 256, n0 = blockIdx.x * 64;
    int rb = warp << 5;

    uint32_t sb = smem_u32(smh);
    uint32_t xa0 = sb + (uint32_t)((rb + (lane & 15)) * SP + ((lane & 16) >> 1)) * 2;
    uint32_t xa1 = xa0 + 16 * SP * 2;
    uint32_t wa = sb + (uint32_t)(256 * SP + ((lane & 7) + ((lane & 16) >> 1)) * SP
                                  + (lane & 8)) * 2;

    float acc[2][8][4] = {};

    for (int k0 = 0; k0 < CC; k0 += 64) {
        __syncthreads();
        #pragma unroll
        for (int i = 0; i < 8; i++) {
            int idx = tid + i * 256;
            int row = idx >> 3, j = idx & 7;
            *(uint4*)(Xs + row * SP + 8 * j) =
                *(const uint4*)(g_att_h + (size_t)(m0 + row) * CC + k0 + 8 * j);
        }
        #pragma unroll
        for (int i = 0; i < 4; i++) {
            int idx = tid + i * 256;
            int row = idx >> 4, j = idx & 15;
            float4 v = *(const float4*)(W + (size_t)(n0 + row) * CC + k0 + 4 * j);
            uint2 st;
            st.x = pack_h2(v.x, v.y); st.y = pack_h2(v.z, v.w);
            *(uint2*)(Ws + row * SP + 4 * j) = st;
        }
        __syncthreads();

        #pragma unroll
        for (int s = 0; s < 4; s++) {
            uint32_t A0[4], A1[4];
            ldsm4(A0[0], A0[1], A0[2], A0[3], xa0 + 32 * s);
            ldsm4(A1[0], A1[1], A1[2], A1[3], xa1 + 32 * s);
            #pragma unroll
            for (int jp = 0; jp < 4; jp++) {
                uint32_t b0, b1, b2, b3;
                ldsm4(b0, b1, b2, b3, wa + jp * (32 * SP) + 32 * s);
                mma16(acc[0][2 * jp], A0[0], A0[1], A0[2], A0[3], b0, b1);
                mma16(acc[0][2 * jp + 1], A0[0], A0[1], A0[2], A0[3], b2, b3);
                mma16(acc[1][2 * jp], A1[0], A1[1], A1[2], A1[3], b0, b1);
                mma16(acc[1][2 * jp + 1], A1[0], A1[1], A1[2], A1[3], b2, b3);
            }
        }
    }

    #pragma unroll
    for (int n = 0; n < 8; n++) {
        int col = n0 + 8 * n + 2 * c4;
        float b0v = B[col], b1v = B[col + 1];
        #pragma unroll
        for (int m = 0; m < 2; m++) {
            int mr0 = m0 + rb + 16 * m + g, mr1 = mr0 + 8;
            *(float2*)(Yout + (size_t)mr0 * CC + col) =
                make_float2(acc[m][n][0] + b0v, acc[m][n][1] + b1v);
            *(float2*)(Yout + (size_t)mr1 * CC + col) =
                make_float2(acc[m][n][2] + b0v, acc[m][n][3] + b1v);
        }
    }
}

// ---------------- decomposed rel-pos bias (fp16 mma) -------------------------
__global__ void __launch_bounds__(128) relpos_kernel(
    const float* __restrict__ rph, const float* __restrict__ rpw)
{
    __shared__ __half Qs[64 * SP];
    __shared__ __half Rs[64 * SP];
    int axis = blockIdx.z, head = blockIdx.y, a0 = blockIdx.x;
    int tid = threadIdx.x;
    int warp = tid >> 5, lane = tid & 31, g = lane >> 2, c4 = lane & 3;

    const float* rp = (axis == 0) ? rph : rpw;
    #pragma unroll
    for (int i = 0; i < 4; i++) {       // Q: 64 rows x 8 uint4
        int idx = tid + i * 128;
        int row = idx >> 3, j = idx & 7;
        int tok = (axis == 0) ? (a0 * 64 + row) : (row * 64 + a0);
        *(uint4*)(Qs + row * SP + 8 * j) =
            *(const uint4*)(g_Q + ((size_t)head * HW + tok) * HD + 8 * j);
    }
    #pragma unroll
    for (int i = 0; i < 8; i++) {       // R: 64 rows x 16 float4 -> half
        int idx = tid + i * 128;
        int row = idx >> 4, j = idx & 15;
        float4 v = *(const float4*)(rp + (size_t)(a0 - row + 63) * HD + 4 * j);
        uint2 st;
        st.x = pack_h2(v.x, v.y); st.y = pack_h2(v.z, v.w);
        *(uint2*)(Rs + row * SP + 4 * j) = st;
    }
    __syncthreads();

    uint32_t sq = smem_u32(Qs), sr = smem_u32(Rs);
    int r0 = warp * 16 + g, r1 = r0 + 8;
    uint32_t qa = sq + (uint32_t)((warp * 16 + (lane & 15)) * SP + ((lane & 16) >> 1)) * 2;
    uint32_t ra = sr + (uint32_t)(((lane & 7) + ((lane & 16) >> 1)) * SP + (lane & 8)) * 2;

    float acc[8][4] = {};
    #pragma unroll
    for (int s = 0; s < 4; s++) {
        uint32_t a0r, a1r, a2r, a3r;
        ldsm4(a0r, a1r, a2r, a3r, qa + 32 * s);
        #pragma unroll
        for (int jp = 0; jp < 4; jp++) {
            uint32_t b0, b1, b2, b3;
            ldsm4(b0, b1, b2, b3, ra + jp * (32 * SP) + 32 * s);
            mma16(acc[2 * jp], a0r, a1r, a2r, a3r, b0, b1);
            mma16(acc[2 * jp + 1], a0r, a1r, a2r, a3r, b2, b3);
        }
    }

    #pragma unroll
    for (int n = 0; n < 8; n++) {
        int k = 8 * n + 2 * c4;
        float v00 = acc[n][0] * 8.f, v01 = acc[n][1] * 8.f;
        float v10 = acc[n][2] * 8.f, v11 = acc[n][3] * 8.f;
        if (axis == 0) {
            int t0 = a0 * 64 + r0, t1 = a0 * 64 + r1;
            g_relh[((size_t)head * HD + k) * HW + t0] = v00;
            g_relh[((size_t)head * HD + k + 1) * HW + t0] = v01;
            g_relh[((size_t)head * HD + k) * HW + t1] = v10;
            g_relh[((size_t)head * HD + k + 1) * HW + t1] = v11;
        } else {
            int t0 = r0 * 64 + a0, t1 = r1 * 64 + a0;
            *(__half2*)(g_relw + ((size_t)head * HW + t0) * HD + k) =
                __floats2half2_rn(v00, v01);
            *(__half2*)(g_relw + ((size_t)head * HW + t1) * HD + k) =
                __floats2half2_rn(v10, v11);
        }
    }
}

// ---------------- flash attention, fp16 mma + ldmatrix -----------------------
// V staged naturally [key][d]; PV B-frags via ldmatrix.trans. Register-P.
__global__ void __launch_bounds__(256, 2) attnmma_kernel()
{
    extern __shared__ __half smh[];
    __half* Qs  = smh;                  // [128][SP]
    __half* Bws = Qs + 128 * SP;        // [128][SP]
    __half* Ks  = Bws + 128 * SP;       // [64][SP]
    __half* Vs  = Ks + 64 * SP;         // [64][SP] natural [key][d]

    int tid = threadIdx.x;
    int warp = tid >> 5, lane = tid & 31, g = lane >> 2, c4 = lane & 3;
    int head = blockIdx.y, q0 = blockIdx.x * 128;
    int r0 = warp * 16 + g, r1 = r0 + 8;

    uint32_t sb = smem_u32(smh);
    uint32_t qa = sb + (uint32_t)((warp * 16 + (lane & 15)) * SP + ((lane & 16) >> 1)) * 2;
    uint32_t ka = sb + (uint32_t)(256 * SP + ((lane & 7) + ((lane & 16) >> 1)) * SP
                                  + (lane & 8)) * 2;
    uint32_t va = sb + (uint32_t)(320 * SP + (lane & 15) * SP + ((lane & 16) >> 1)) * 2;

    size_t qb = (size_t)head * HW + q0;
    #pragma unroll
    for (int i = 0; i < 4; i++) {
        int idx = tid + i * 256;
        int row = idx >> 3, j = idx & 7;
        *(uint4*)(Qs + row * SP + 8 * j) =
            *(const uint4*)(g_Q + (qb + row) * HD + 8 * j);
        *(uint4*)(Bws + row * SP + 8 * j) =
            *(const uint4*)(g_relw + (qb + row) * HD + 8 * j);
    }

    const float* rh0 = g_relh + (size_t)head * HD * HW + q0;
    float nbh0 = rh0[r0], nbh1 = rh0[r1];

    float O[8][4] = {};
    float l0 = 0.f, l1 = 0.f;

    for (int kt = 0; kt < HW / 64; kt++) {
        __syncthreads();
        size_t kb = (size_t)head * HW + kt * 64;
        #pragma unroll
        for (int i = 0; i < 2; i++) {                 // K + V: coalesced copies
            int idx = tid + i * 256;
            int row = idx >> 3, j = idx & 7;
            *(uint4*)(Ks + row * SP + 8 * j) =
                *(const uint4*)(g_K + (kb + row) * HD + 8 * j);
            *(uint4*)(Vs + row * SP + 8 * j) =
                *(const uint4*)(g_V + (kb + row) * HD + 8 * j);
        }
        float bh0 = nbh0, bh1 = nbh1;
        __syncthreads();

        if (kt + 1 < HW / 64) {
            const float* rh = g_relh + ((size_t)head * HD + kt + 1) * HW + q0;
            nbh0 = rh[r0]; nbh1 = rh[r1];
        }

        // ---- S = bias; S += Qs @ K^T ----
        float S[8][4];
        #pragma unroll
        for (int n = 0; n < 8; n++) {
            int col = 8 * n + 2 * c4;
            float2 w0 = __half22float2(*(const __half2*)(Bws + r0 * SP + col));
            float2 w1 = __half22float2(*(const __half2*)(Bws + r1 * SP + col));
            S[n][0] = bh0 + w0.x; S[n][1] = bh0 + w0.y;
            S[n][2] = bh1 + w1.x; S[n][3] = bh1 + w1.y;
        }
        #pragma unroll
        for (int s = 0; s < 4; s++) {
            uint32_t a0, a1, a2, a3;
            ldsm4(a0, a1, a2, a3, qa + 32 * s);
            #pragma unroll
            for (int jp = 0; jp < 4; jp++) {
                uint32_t b0, b1, b2, b3;
                ldsm4(b0, b1, b2, b3, ka + jp * (32 * SP) + 32 * s);
                mma16(S[2 * jp], a0, a1, a2, a3, b0, b1);
                mma16(S[2 * jp + 1], a0, a1, a2, a3, b2, b3);
            }
        }

        // ---- softmax without max: p = ex2(s), pack ----
        uint32_t hr0[8], hr1[8];
        float s0 = 0.f, s1 = 0.f;
        #pragma unroll
        for (int n = 0; n < 8; n++) {
            float p00 = ex2f(S[n][0]), p01 = ex2f(S[n][1]);
            float p10 = ex2f(S[n][2]), p11 = ex2f(S[n][3]);
            s0 += p00 + p01; s1 += p10 + p11;
            hr0[n] = pack_h2(p00, p01);
            hr1[n] = pack_h2(p10, p11);
        }
        s0 += __shfl_xor_sync(0xffffffffu, s0, 1);
        s0 += __shfl_xor_sync(0xffffffffu, s0, 2);
        s1 += __shfl_xor_sync(0xffffffffu, s1, 1);
        s1 += __shfl_xor_sync(0xffffffffu, s1, 2);
        l0 += s0; l1 += s1;

        // ---- O += P @ V : A from regs, B via ldmatrix.trans ----
        #pragma unroll
        for (int s = 0; s < 4; s++) {
            uint32_t a0 = hr0[2 * s], a1 = hr1[2 * s];
            uint32_t a2 = hr0[2 * s + 1], a3 = hr1[2 * s + 1];
            #pragma unroll
            for (int jp = 0; jp < 4; jp++) {
                uint32_t b0, b1, b2, b3;
                ldsm4t(b0, b1, b2, b3, va + s * (32 * SP) + jp * 32);
                mma16(O[2 * jp], a0, a1, a2, a3, b0, b1);
                mma16(O[2 * jp + 1], a0, a1, a2, a3, b2, b3);
            }
        }
    }

    float inv0 = 1.0f / l0, inv1 = 1.0f / l1;
    #pragma unroll
    for (int n = 0; n < 8; n++) {
        int d = 8 * n + 2 * c4;
        *(__half2*)(g_att_h + (size_t)(q0 + r0) * CC + head * HD + d) =
            __floats2half2_rn(O[n][0] * inv0, O[n][1] * inv0);
        *(__half2*)(g_att_h + (size_t)(q0 + r1) * CC + head * HD + d) =
            __floats2half2_rn(O[n][2] * inv1, O[n][3] * inv1);
    }
}

// ---------------- launch -----------------------------------------------------
extern "C" void kernel_launch(void* const* d_in, const int* in_sizes, int n_in,
                              void* d_out, int out_size)
{
    const float* hs  = (const float*)d_in[0];
    const float* w_q = (const float*)d_in[1];
    const float* b_q = (const float*)d_in[2];
    const float* w_k = (const float*)d_in[3];
    const float* b_k = (const float*)d_in[4];
    const float* w_v = (const float*)d_in[5];
    const float* b_v = (const float*)d_in[6];
    const float* w_o = (const float*)d_in[7];
    const float* b_o = (const float*)d_in[8];
    const float* rph = (const float*)d_in[9];
    const float* rpw = (const float*)d_in[10];
    float* out = (float*)d_out;

    int proj_smem = (256 * SP + 64 * SP) * (int)sizeof(__half);           // 46080 B
    int att_smem  = (2 * 128 * SP + 2 * 64 * SP) * (int)sizeof(__half);   // 55296 B

    cudaFuncSetAttribute(projqkv_kernel, cudaFuncAttributeMaxDynamicSharedMemorySize, proj_smem);
    cudaFuncSetAttribute(projout_kernel, cudaFuncAttributeMaxDynamicSharedMemorySize, proj_smem);
    cudaFuncSetAttribute(attnmma_kernel, cudaFuncAttributeMaxDynamicSharedMemorySize, att_smem);

    cvt_kernel<<<HW * CC / 1024, 256>>>(hs);

    projqkv_kernel<<<dim3(CC / 64, HW / 256, 3), 256, proj_smem>>>(
        w_q, b_q, w_k, b_k, w_v, b_v);

    relpos_kernel<<<dim3(64, NHEADS, 2), 128>>>(rph, rpw);

    attnmma_kernel<<<dim3(HW / 128, NHEADS), 256, att_smem>>>();

    projout_kernel<<<dim3(CC / 64, HW / 256), 256, proj_smem>>>(w_o, b_o, out);
}

// round 14
// speedup vs baseline: 3.4777x; 1.0733x over previous
#include <cuda_runtime.h>
#include <cuda_fp16.h>
#include <math.h>
#include <stdint.h>

#define HW 4096
#define CC 768
#define NHEADS 12
#define HD 64
#define SP 72   // smem stride in halves; 144B rows -> ldmatrix conflict-free

// ---------------- scratch ----------------------------------------------------
__device__ __half g_Xh[(size_t)HW * CC];            // hidden_states, half
__device__ __half g_Q[(size_t)NHEADS * HW * HD];    // q * 0.125 * log2e
__device__ __half g_K[(size_t)NHEADS * HW * HD];
__device__ __half g_V[(size_t)NHEADS * HW * HD];
__device__ float  g_relh[(size_t)NHEADS * HD * HW]; // [head][kh][tok], *log2e
__device__ __half g_relw[(size_t)NHEADS * HW * HD]; // [head][tok][kw], *log2e
__device__ __half g_att_h[(size_t)HW * CC];         // attention out, half

// ---------------- helpers ----------------------------------------------------
__device__ __forceinline__ float ex2f(float x) {
    float y;
    asm("ex2.approx.f32 %0, %1;" : "=f"(y) : "f"(x));
    return y;
}
__device__ __forceinline__ uint32_t pack_h2(float a, float b) {
    __half2 h = __floats2half2_rn(a, b);
    return *reinterpret_cast<uint32_t*>(&h);
}
__device__ __forceinline__ uint32_t smem_u32(const void* p) {
    uint32_t a;
    asm("{ .reg .u64 t; cvta.to.shared.u64 t, %1; cvt.u32.u64 %0, t; }"
        : "=r"(a) : "l"(p));
    return a;
}
__device__ __forceinline__ void mma16(float* c,
                                      uint32_t a0, uint32_t a1, uint32_t a2, uint32_t a3,
                                      uint32_t b0, uint32_t b1) {
    asm volatile(
        "mma.sync.aligned.m16n8k16.row.col.f32.f16.f16.f32 "
        "{%0,%1,%2,%3}, {%4,%5,%6,%7}, {%8,%9}, {%0,%1,%2,%3};\n"
        : "+f"(c[0]), "+f"(c[1]), "+f"(c[2]), "+f"(c[3])
        : "r"(a0), "r"(a1), "r"(a2), "r"(a3), "r"(b0), "r"(b1));
}
__device__ __forceinline__ void ldsm4(uint32_t& r0, uint32_t& r1, uint32_t& r2,
                                      uint32_t& r3, uint32_t a) {
    asm volatile("ldmatrix.sync.aligned.m8n8.x4.shared.b16 {%0,%1,%2,%3}, [%4];"
                 : "=r"(r0), "=r"(r1), "=r"(r2), "=r"(r3) : "r"(a));
}
__device__ __forceinline__ void ldsm4t(uint32_t& r0, uint32_t& r1, uint32_t& r2,
                                       uint32_t& r3, uint32_t a) {
    asm volatile("ldmatrix.sync.aligned.m8n8.x4.trans.shared.b16 {%0,%1,%2,%3}, [%4];"
                 : "=r"(r0), "=r"(r1), "=r"(r2), "=r"(r3) : "r"(a));
}
#define CP16(dst, src) \
    asm volatile("cp.async.cg.shared.global [%0], [%1], 16;" :: "r"(dst), "l"(src))
#define CP_COMMIT() asm volatile("cp.async.commit_group;" ::: "memory")
#define CP_WAIT(n)  asm volatile("cp.async.wait_group %0;" :: "n"(n) : "memory")

// ---------------- X fp32 -> half ---------------------------------------------
__global__ void __launch_bounds__(256) cvt_kernel(const float* __restrict__ hs)
{
    size_t i = ((size_t)blockIdx.x * 256 + threadIdx.x) * 4;
    float4 v = *(const float4*)(hs + i);
    uint2 st;
    st.x = pack_h2(v.x, v.y); st.y = pack_h2(v.z, v.w);
    *(uint2*)&g_Xh[i] = st;
}

// ---------------- fused QKV projection (fp16 mma + ldmatrix) -----------------
__global__ void __launch_bounds__(256, 2) projqkv_kernel(
    const float* __restrict__ wq, const float* __restrict__ bq,
    const float* __restrict__ wk, const float* __restrict__ bk,
    const float* __restrict__ wv, const float* __restrict__ bv)
{
    extern __shared__ __half smh[];
    __half* Xs = smh;              // [256][SP]
    __half* Ws = smh + 256 * SP;   // [64][SP]

    int z = blockIdx.z;
    const float* W = (z == 0) ? wq : (z == 1) ? wk : wv;
    const float* B = (z == 0) ? bq : (z == 1) ? bk : bv;
    __half* dst = (z == 0) ? g_Q : (z == 1) ? g_K : g_V;
    const float scale = (z == 0) ? 0.125f * 1.44269504f : 1.0f;

    int tid = threadIdx.x;
    int warp = tid >> 5, lane = tid & 31, g = lane >> 2, c4 = lane & 3;
    int m0 = blockIdx.y * 256, n0 = blockIdx.x * 64;
    int rb = warp << 5;

    uint32_t sb = smem_u32(smh);
    uint32_t xa0 = sb + (uint32_t)((rb + (lane & 15)) * SP + ((lane & 16) >> 1)) * 2;
    uint32_t xa1 = xa0 + 16 * SP * 2;
    uint32_t wa = sb + (uint32_t)(256 * SP + ((lane & 7) + ((lane & 16) >> 1)) * SP
                                  + (lane & 8)) * 2;

    float acc[2][8][4] = {};

    for (int k0 = 0; k0 < CC; k0 += 64) {
        __syncthreads();
        #pragma unroll
        for (int i = 0; i < 8; i++) {
            int idx = tid + i * 256;
            int row = idx >> 3, j = idx & 7;
            *(uint4*)(Xs + row * SP + 8 * j) =
                *(const uint4*)(g_Xh + (size_t)(m0 + row) * CC + k0 + 8 * j);
        }
        #pragma unroll
        for (int i = 0; i < 4; i++) {
            int idx = tid + i * 256;
            int row = idx >> 4, j = idx & 15;
            float4 v = *(const float4*)(W + (size_t)(n0 + row) * CC + k0 + 4 * j);
            uint2 st;
            st.x = pack_h2(v.x, v.y); st.y = pack_h2(v.z, v.w);
            *(uint2*)(Ws + row * SP + 4 * j) = st;
        }
        __syncthreads();

        #pragma unroll
        for (int s = 0; s < 4; s++) {
            uint32_t A0[4], A1[4];
            ldsm4(A0[0], A0[1], A0[2], A0[3], xa0 + 32 * s);
            ldsm4(A1[0], A1[1], A1[2], A1[3], xa1 + 32 * s);
            #pragma unroll
            for (int jp = 0; jp < 4; jp++) {
                uint32_t b0, b1, b2, b3;
                ldsm4(b0, b1, b2, b3, wa + jp * (32 * SP) + 32 * s);
                mma16(acc[0][2 * jp], A0[0], A0[1], A0[2], A0[3], b0, b1);
                mma16(acc[0][2 * jp + 1], A0[0], A0[1], A0[2], A0[3], b2, b3);
                mma16(acc[1][2 * jp], A1[0], A1[1], A1[2], A1[3], b0, b1);
                mma16(acc[1][2 * jp + 1], A1[0], A1[1], A1[2], A1[3], b2, b3);
            }
        }
    }

    #pragma unroll
    for (int n = 0; n < 8; n++) {
        int col = n0 + 8 * n + 2 * c4;
        float b0v = B[col], b1v = B[col + 1];
        size_t base = (size_t)(col >> 6) * HW;
        #pragma unroll
        for (int m = 0; m < 2; m++) {
            int mr0 = m0 + rb + 16 * m + g, mr1 = mr0 + 8;
            *(__half2*)(dst + (base + mr0) * HD + (col & 63)) =
                __floats2half2_rn((acc[m][n][0] + b0v) * scale,
                                  (acc[m][n][1] + b1v) * scale);
            *(__half2*)(dst + (base + mr1) * HD + (col & 63)) =
                __floats2half2_rn((acc[m][n][2] + b0v) * scale,
                                  (acc[m][n][3] + b1v) * scale);
        }
    }
}

// ---------------- output projection (fp16 mma + ldmatrix, fp32 out) ----------
__global__ void __launch_bounds__(256, 2) projout_kernel(
    const float* __restrict__ W, const float* __restrict__ B,
    float* __restrict__ Yout)
{
    extern __shared__ __half smh[];
    __half* Xs = smh;
    __half* Ws = smh + 256 * SP;

    int tid = threadIdx.x;
    int warp = tid >> 5, lane = tid & 31, g = lane >> 2, c4 = lane & 3;
    int m0 = blockIdx.y * 256, n0 = blockIdx.x * 64;
    int rb = warp << 5;

    uint32_t sb = smem_u32(smh);
    uint32_t xa0 = sb + (uint32_t)((rb + (lane & 15)) * SP + ((lane & 16) >> 1)) * 2;
    uint32_t xa1 = xa0 + 16 * SP * 2;
    uint32_t wa = sb + (uint32_t)(256 * SP + ((lane & 7) + ((lane & 16) >> 1)) * SP
                                  + (lane & 8)) * 2;

    float acc[2][8][4] = {};

    for (int k0 = 0; k0 < CC; k0 += 64) {
        __syncthreads();
        #pragma unroll
        for (int i = 0; i < 8; i++) {
            int idx = tid + i * 256;
            int row = idx >> 3, j = idx & 7;
            *(uint4*)(Xs + row * SP + 8 * j) =
                *(const uint4*)(g_att_h + (size_t)(m0 + row) * CC + k0 + 8 * j);
        }
        #pragma unroll
        for (int i = 0; i < 4; i++) {
            int idx = tid + i * 256;
            int row = idx >> 4, j = idx & 15;
            float4 v = *(const float4*)(W + (size_t)(n0 + row) * CC + k0 + 4 * j);
            uint2 st;
            st.x = pack_h2(v.x, v.y); st.y = pack_h2(v.z, v.w);
            *(uint2*)(Ws + row * SP + 4 * j) = st;
        }
        __syncthreads();

        #pragma unroll
        for (int s = 0; s < 4; s++) {
            uint32_t A0[4], A1[4];
            ldsm4(A0[0], A0[1], A0[2], A0[3], xa0 + 32 * s);
            ldsm4(A1[0], A1[1], A1[2], A1[3], xa1 + 32 * s);
            #pragma unroll
            for (int jp = 0; jp < 4; jp++) {
                uint32_t b0, b1, b2, b3;
                ldsm4(b0, b1, b2, b3, wa + jp * (32 * SP) + 32 * s);
                mma16(acc[0][2 * jp], A0[0], A0[1], A0[2], A0[3], b0, b1);
                mma16(acc[0][2 * jp + 1], A0[0], A0[1], A0[2], A0[3], b2, b3);
                mma16(acc[1][2 * jp], A1[0], A1[1], A1[2], A1[3], b0, b1);
                mma16(acc[1][2 * jp + 1], A1[0], A1[1], A1[2], A1[3], b2, b3);
            }
        }
    }

    #pragma unroll
    for (int n = 0; n < 8; n++) {
        int col = n0 + 8 * n + 2 * c4;
        float b0v = B[col], b1v = B[col + 1];
        #pragma unroll
        for (int m = 0; m < 2; m++) {
            int mr0 = m0 + rb + 16 * m + g, mr1 = mr0 + 8;
            *(float2*)(Yout + (size_t)mr0 * CC + col) =
                make_float2(acc[m][n][0] + b0v, acc[m][n][1] + b1v);
            *(float2*)(Yout + (size_t)mr1 * CC + col) =
                make_float2(acc[m][n][2] + b0v, acc[m][n][3] + b1v);
        }
    }
}

// ---------------- decomposed rel-pos bias (fp16 mma) -------------------------
__global__ void __launch_bounds__(128) relpos_kernel(
    const float* __restrict__ rph, const float* __restrict__ rpw)
{
    __shared__ __half Qs[64 * SP];
    __shared__ __half Rs[64 * SP];
    int axis = blockIdx.z, head = blockIdx.y, a0 = blockIdx.x;
    int tid = threadIdx.x;
    int warp = tid >> 5, lane = tid & 31, g = lane >> 2, c4 = lane & 3;

    const float* rp = (axis == 0) ? rph : rpw;
    #pragma unroll
    for (int i = 0; i < 4; i++) {
        int idx = tid + i * 128;
        int row = idx >> 3, j = idx & 7;
        int tok = (axis == 0) ? (a0 * 64 + row) : (row * 64 + a0);
        *(uint4*)(Qs + row * SP + 8 * j) =
            *(const uint4*)(g_Q + ((size_t)head * HW + tok) * HD + 8 * j);
    }
    #pragma unroll
    for (int i = 0; i < 8; i++) {
        int idx = tid + i * 128;
        int row = idx >> 4, j = idx & 15;
        float4 v = *(const float4*)(rp + (size_t)(a0 - row + 63) * HD + 4 * j);
        uint2 st;
        st.x = pack_h2(v.x, v.y); st.y = pack_h2(v.z, v.w);
        *(uint2*)(Rs + row * SP + 4 * j) = st;
    }
    __syncthreads();

    uint32_t sq = smem_u32(Qs), sr = smem_u32(Rs);
    int r0 = warp * 16 + g, r1 = r0 + 8;
    uint32_t qa = sq + (uint32_t)((warp * 16 + (lane & 15)) * SP + ((lane & 16) >> 1)) * 2;
    uint32_t ra = sr + (uint32_t)(((lane & 7) + ((lane & 16) >> 1)) * SP + (lane & 8)) * 2;

    float acc[8][4] = {};
    #pragma unroll
    for (int s = 0; s < 4; s++) {
        uint32_t a0r, a1r, a2r, a3r;
        ldsm4(a0r, a1r, a2r, a3r, qa + 32 * s);
        #pragma unroll
        for (int jp = 0; jp < 4; jp++) {
            uint32_t b0, b1, b2, b3;
            ldsm4(b0, b1, b2, b3, ra + jp * (32 * SP) + 32 * s);
            mma16(acc[2 * jp], a0r, a1r, a2r, a3r, b0, b1);
            mma16(acc[2 * jp + 1], a0r, a1r, a2r, a3r, b2, b3);
        }
    }

    #pragma unroll
    for (int n = 0; n < 8; n++) {
        int k = 8 * n + 2 * c4;
        float v00 = acc[n][0] * 8.f, v01 = acc[n][1] * 8.f;
        float v10 = acc[n][2] * 8.f, v11 = acc[n][3] * 8.f;
        if (axis == 0) {
            int t0 = a0 * 64 + r0, t1 = a0 * 64 + r1;
            g_relh[((size_t)head * HD + k) * HW + t0] = v00;
            g_relh[((size_t)head * HD + k + 1) * HW + t0] = v01;
            g_relh[((size_t)head * HD + k) * HW + t1] = v10;
            g_relh[((size_t)head * HD + k + 1) * HW + t1] = v11;
        } else {
            int t0 = r0 * 64 + a0, t1 = r1 * 64 + a0;
            *(__half2*)(g_relw + ((size_t)head * HW + t0) * HD + k) =
                __floats2half2_rn(v00, v01);
            *(__half2*)(g_relw + ((size_t)head * HW + t1) * HD + k) =
                __floats2half2_rn(v10, v11);
        }
    }
}

// ---------------- flash attention: ldmatrix + cp.async double buffer ---------
// smem halves: Qs[128*SP] Bws[128*SP] K[2][64*SP] V[2][64*SP] = 73728 B.
__global__ void __launch_bounds__(256, 2) attnmma_kernel()
{
    extern __shared__ __half smh[];
    __half* Qs  = smh;                   // [128][SP]
    __half* Bws = Qs + 128 * SP;         // [128][SP]
    const int KOFF = 256 * SP;           // K stages at 256*SP, 320*SP
    const int VOFF = 384 * SP;           // V stages at 384*SP, 448*SP

    int tid = threadIdx.x;
    int warp = tid >> 5, lane = tid & 31, g = lane >> 2, c4 = lane & 3;
    int head = blockIdx.y, q0 = blockIdx.x * 128;
    int r0 = warp * 16 + g, r1 = r0 + 8;

    uint32_t sb = smem_u32(smh);
    uint32_t qa = sb + (uint32_t)((warp * 16 + (lane & 15)) * SP + ((lane & 16) >> 1)) * 2;
    uint32_t ka_b = sb + (uint32_t)(KOFF + ((lane & 7) + ((lane & 16) >> 1)) * SP
                                    + (lane & 8)) * 2;
    uint32_t va_b = sb + (uint32_t)(VOFF + (lane & 15) * SP + ((lane & 16) >> 1)) * 2;

    int r_st = tid >> 3, j_st = tid & 7;            // staging row/col4 (i adds 32 rows)
    size_t hb = (size_t)head * HW;

    // ---- issue cp.async for tile 0 into stage 0, then stage Q/Bws ----
    #pragma unroll
    for (int i = 0; i < 2; i++) {
        int row = r_st + 32 * i;
        uint32_t dk = sb + (uint32_t)(KOFF + row * SP + 8 * j_st) * 2;
        uint32_t dv = sb + (uint32_t)(VOFF + row * SP + 8 * j_st) * 2;
        CP16(dk, g_K + (hb + row) * HD + 8 * j_st);
        CP16(dv, g_V + (hb + row) * HD + 8 * j_st);
    }
    CP_COMMIT();

    size_t qb = hb + q0;
    #pragma unroll
    for (int i = 0; i < 4; i++) {
        int idx = tid + i * 256;
        int row = idx >> 3, j = idx & 7;
        *(uint4*)(Qs + row * SP + 8 * j) =
            *(const uint4*)(g_Q + (qb + row) * HD + 8 * j);
        *(uint4*)(Bws + row * SP + 8 * j) =
            *(const uint4*)(g_relw + (qb + row) * HD + 8 * j);
    }

    const float* rh0 = g_relh + (size_t)head * HD * HW + q0;
    float nbh0 = rh0[r0], nbh1 = rh0[r1];

    float O[8][4] = {};
    float l0 = 0.f, l1 = 0.f;

    for (int kt = 0; kt < HW / 64; kt++) {
        int p = kt & 1;
        __syncthreads();   // all warps done reading stage p^1 (tile kt-1)
        if (kt + 1 < HW / 64) {
            size_t kb = hb + (size_t)(kt + 1) * 64;
            int st = (p ^ 1) * 64 * SP;
            #pragma unroll
            for (int i = 0; i < 2; i++) {
                int row = r_st + 32 * i;
                uint32_t dk = sb + (uint32_t)(KOFF + st + row * SP + 8 * j_st) * 2;
                uint32_t dv = sb + (uint32_t)(VOFF + st + row * SP + 8 * j_st) * 2;
                CP16(dk, g_K + (kb + row) * HD + 8 * j_st);
                CP16(dv, g_V + (kb + row) * HD + 8 * j_st);
            }
            CP_COMMIT();
            CP_WAIT(1);    // tile kt's group complete
        } else {
            CP_WAIT(0);
        }
        float bh0 = nbh0, bh1 = nbh1;
        __syncthreads();   // stage p data visible to all warps

        if (kt + 1 < HW / 64) {
            const float* rh = g_relh + ((size_t)head * HD + kt + 1) * HW + q0;
            nbh0 = rh[r0]; nbh1 = rh[r1];
        }

        uint32_t ka = ka_b + (uint32_t)(p * 64 * SP) * 2;
        uint32_t va = va_b + (uint32_t)(p * 64 * SP) * 2;

        // ---- S = bias; S += Qs @ K^T ----
        float S[8][4];
        #pragma unroll
        for (int n = 0; n < 8; n++) {
            int col = 8 * n + 2 * c4;
            float2 w0 = __half22float2(*(const __half2*)(Bws + r0 * SP + col));
            float2 w1 = __half22float2(*(const __half2*)(Bws + r1 * SP + col));
            S[n][0] = bh0 + w0.x; S[n][1] = bh0 + w0.y;
            S[n][2] = bh1 + w1.x; S[n][3] = bh1 + w1.y;
        }
        #pragma unroll
        for (int s = 0; s < 4; s++) {
            uint32_t a0, a1, a2, a3;
            ldsm4(a0, a1, a2, a3, qa + 32 * s);
            #pragma unroll
            for (int jp = 0; jp < 4; jp++) {
                uint32_t b0, b1, b2, b3;
                ldsm4(b0, b1, b2, b3, ka + jp * (32 * SP) + 32 * s);
                mma16(S[2 * jp], a0, a1, a2, a3, b0, b1);
                mma16(S[2 * jp + 1], a0, a1, a2, a3, b2, b3);
            }
        }

        // ---- softmax without max: p = ex2(s), pack ----
        uint32_t hr0[8], hr1[8];
        float s0 = 0.f, s1 = 0.f;
        #pragma unroll
        for (int n = 0; n < 8; n++) {
            float p00 = ex2f(S[n][0]), p01 = ex2f(S[n][1]);
            float p10 = ex2f(S[n][2]), p11 = ex2f(S[n][3]);
            s0 += p00 + p01; s1 += p10 + p11;
            hr0[n] = pack_h2(p00, p01);
            hr1[n] = pack_h2(p10, p11);
        }
        s0 += __shfl_xor_sync(0xffffffffu, s0, 1);
        s0 += __shfl_xor_sync(0xffffffffu, s0, 2);
        s1 += __shfl_xor_sync(0xffffffffu, s1, 1);
        s1 += __shfl_xor_sync(0xffffffffu, s1, 2);
        l0 += s0; l1 += s1;

        // ---- O += P @ V : A from regs, B via ldmatrix.trans ----
        #pragma unroll
        for (int s = 0; s < 4; s++) {
            uint32_t a0 = hr0[2 * s], a1 = hr1[2 * s];
            uint32_t a2 = hr0[2 * s + 1], a3 = hr1[2 * s + 1];
            #pragma unroll
            for (int jp = 0; jp < 4; jp++) {
                uint32_t b0, b1, b2, b3;
                ldsm4t(b0, b1, b2, b3, va + s * (32 * SP) + jp * 32);
                mma16(O[2 * jp], a0, a1, a2, a3, b0, b1);
                mma16(O[2 * jp + 1], a0, a1, a2, a3, b2, b3);
            }
        }
    }

    float inv0 = 1.0f / l0, inv1 = 1.0f / l1;
    #pragma unroll
    for (int n = 0; n < 8; n++) {
        int d = 8 * n + 2 * c4;
        *(__half2*)(g_att_h + (size_t)(q0 + r0) * CC + head * HD + d) =
            __floats2half2_rn(O[n][0] * inv0, O[n][1] * inv0);
        *(__half2*)(g_att_h + (size_t)(q0 + r1) * CC + head * HD + d) =
            __floats2half2_rn(O[n][2] * inv1, O[n][3] * inv1);
    }
}

// ---------------- launch -----------------------------------------------------
extern "C" void kernel_launch(void* const* d_in, const int* in_sizes, int n_in,
                              void* d_out, int out_size)
{
    const float* hs  = (const float*)d_in[0];
    const float* w_q = (const float*)d_in[1];
    const float* b_q = (const float*)d_in[2];
    const float* w_k = (const float*)d_in[3];
    const float* b_k = (const float*)d_in[4];
    const float* w_v = (const float*)d_in[5];
    const float* b_v = (const float*)d_in[6];
    const float* w_o = (const float*)d_in[7];
    const float* b_o = (const float*)d_in[8];
    const float* rph = (const float*)d_in[9];
    const float* rpw = (const float*)d_in[10];
    float* out = (float*)d_out;

    int proj_smem = (256 * SP + 64 * SP) * (int)sizeof(__half);           // 46080 B
    int att_smem  = (2 * 128 * SP + 4 * 64 * SP) * (int)sizeof(__half);   // 73728 B

    cudaFuncSetAttribute(projqkv_kernel, cudaFuncAttributeMaxDynamicSharedMemorySize, proj_smem);
    cudaFuncSetAttribute(projout_kernel, cudaFuncAttributeMaxDynamicSharedMemorySize, proj_smem);
    cudaFuncSetAttribute(attnmma_kernel, cudaFuncAttributeMaxDynamicSharedMemorySize, att_smem);

    cvt_kernel<<<HW * CC / 1024, 256>>>(hs);

    projqkv_kernel<<<dim3(CC / 64, HW / 256, 3), 256, proj_smem>>>(
        w_q, b_q, w_k, b_k, w_v, b_v);

    relpos_kernel<<<dim3(64, NHEADS, 2), 128>>>(rph, rpw);

    attnmma_kernel<<<dim3(HW / 128, NHEADS), 256, att_smem>>>();

    projout_kernel<<<dim3(CC / 64, HW / 256), 256, proj_smem>>>(w_o, b_o, out);
}

// round 15
// speedup vs baseline: 3.5054x; 1.0080x over previous
#include <cuda_runtime.h>
#include <cuda_fp16.h>
#include <math.h>
#include <stdint.h>

#define HW 4096
#define CC 768
#define NHEADS 12
#define HD 64
#define SP 72   // smem stride in halves; 144B rows -> ldmatrix conflict-free

// ---------------- scratch ----------------------------------------------------
__device__ __half g_Xh[(size_t)HW * CC];            // hidden_states, half
__device__ __half g_Q[(size_t)NHEADS * HW * HD];    // q * 0.125 * log2e
__device__ __half g_K[(size_t)NHEADS * HW * HD];
__device__ __half g_V[(size_t)NHEADS * HW * HD];
__device__ float  g_relh[(size_t)NHEADS * HD * HW]; // [head][kh][tok], *log2e
__device__ __half g_relw[(size_t)NHEADS * HW * HD]; // [head][tok][kw], *log2e
__device__ __half g_att_h[(size_t)HW * CC];         // attention out, half

// ---------------- helpers ----------------------------------------------------
__device__ __forceinline__ float ex2f(float x) {
    float y;
    asm("ex2.approx.f32 %0, %1;" : "=f"(y) : "f"(x));
    return y;
}
__device__ __forceinline__ uint32_t pack_h2(float a, float b) {
    __half2 h = __floats2half2_rn(a, b);
    return *reinterpret_cast<uint32_t*>(&h);
}
__device__ __forceinline__ uint32_t smem_u32(const void* p) {
    uint32_t a;
    asm("{ .reg .u64 t; cvta.to.shared.u64 t, %1; cvt.u32.u64 %0, t; }"
        : "=r"(a) : "l"(p));
    return a;
}
__device__ __forceinline__ void mma16(float* c,
                                      uint32_t a0, uint32_t a1, uint32_t a2, uint32_t a3,
                                      uint32_t b0, uint32_t b1) {
    asm volatile(
        "mma.sync.aligned.m16n8k16.row.col.f32.f16.f16.f32 "
        "{%0,%1,%2,%3}, {%4,%5,%6,%7}, {%8,%9}, {%0,%1,%2,%3};\n"
        : "+f"(c[0]), "+f"(c[1]), "+f"(c[2]), "+f"(c[3])
        : "r"(a0), "r"(a1), "r"(a2), "r"(a3), "r"(b0), "r"(b1));
}
__device__ __forceinline__ void ldsm4(uint32_t& r0, uint32_t& r1, uint32_t& r2,
                                      uint32_t& r3, uint32_t a) {
    asm volatile("ldmatrix.sync.aligned.m8n8.x4.shared.b16 {%0,%1,%2,%3}, [%4];"
                 : "=r"(r0), "=r"(r1), "=r"(r2), "=r"(r3) : "r"(a));
}
__device__ __forceinline__ void ldsm4t(uint32_t& r0, uint32_t& r1, uint32_t& r2,
                                       uint32_t& r3, uint32_t a) {
    asm volatile("ldmatrix.sync.aligned.m8n8.x4.trans.shared.b16 {%0,%1,%2,%3}, [%4];"
                 : "=r"(r0), "=r"(r1), "=r"(r2), "=r"(r3) : "r"(a));
}
#define CP16(dst, src) \
    asm volatile("cp.async.cg.shared.global [%0], [%1], 16;" :: "r"(dst), "l"(src))
#define CP_COMMIT() asm volatile("cp.async.commit_group;" ::: "memory")
#define CP_WAIT(n)  asm volatile("cp.async.wait_group %0;" :: "n"(n) : "memory")

// ---------------- X fp32 -> half ---------------------------------------------
__global__ void __launch_bounds__(256) cvt_kernel(const float* __restrict__ hs)
{
    size_t i = ((size_t)blockIdx.x * 256 + threadIdx.x) * 4;
    float4 v = *(const float4*)(hs + i);
    uint2 st;
    st.x = pack_h2(v.x, v.y); st.y = pack_h2(v.z, v.w);
    *(uint2*)&g_Xh[i] = st;
}

// ---------------- fused QKV projection (fp16 mma + ldmatrix) -----------------
__global__ void __launch_bounds__(256, 2) projqkv_kernel(
    const float* __restrict__ wq, const float* __restrict__ bq,
    const float* __restrict__ wk, const float* __restrict__ bk,
    const float* __restrict__ wv, const float* __restrict__ bv)
{
    extern __shared__ __half smh[];
    __half* Xs = smh;              // [256][SP]
    __half* Ws = smh + 256 * SP;   // [64][SP]

    int z = blockIdx.z;
    const float* W = (z == 0) ? wq : (z == 1) ? wk : wv;
    const float* B = (z == 0) ? bq : (z == 1) ? bk : bv;
    __half* dst = (z == 0) ? g_Q : (z == 1) ? g_K : g_V;
    const float scale = (z == 0) ? 0.125f * 1.44269504f : 1.0f;

    int tid = threadIdx.x;
    int warp = tid >> 5, lane = tid & 31, g = lane >> 2, c4 = lane & 3;
    int m0 = blockIdx.y * 256, n0 = blockIdx.x * 64;
    int rb = warp << 5;

    uint32_t sb = smem_u32(smh);
    uint32_t xa0 = sb + (uint32_t)((rb + (lane & 15)) * SP + ((lane & 16) >> 1)) * 2;
    uint32_t xa1 = xa0 + 16 * SP * 2;
    uint32_t wa = sb + (uint32_t)(256 * SP + ((lane & 7) + ((lane & 16) >> 1)) * SP
                                  + (lane & 8)) * 2;

    float acc[2][8][4] = {};

    for (int k0 = 0; k0 < CC; k0 += 64) {
        __syncthreads();
        #pragma unroll
        for (int i = 0; i < 8; i++) {
            int idx = tid + i * 256;
            int row = idx >> 3, j = idx & 7;
            *(uint4*)(Xs + row * SP + 8 * j) =
                *(const uint4*)(g_Xh + (size_t)(m0 + row) * CC + k0 + 8 * j);
        }
        #pragma unroll
        for (int i = 0; i < 4; i++) {
            int idx = tid + i * 256;
            int row = idx >> 4, j = idx & 15;
            float4 v = *(const float4*)(W + (size_t)(n0 + row) * CC + k0 + 4 * j);
            uint2 st;
            st.x = pack_h2(v.x, v.y); st.y = pack_h2(v.z, v.w);
            *(uint2*)(Ws + row * SP + 4 * j) = st;
        }
        __syncthreads();

        #pragma unroll
        for (int s = 0; s < 4; s++) {
            uint32_t A0[4], A1[4];
            ldsm4(A0[0], A0[1], A0[2], A0[3], xa0 + 32 * s);
            ldsm4(A1[0], A1[1], A1[2], A1[3], xa1 + 32 * s);
            #pragma unroll
            for (int jp = 0; jp < 4; jp++) {
                uint32_t b0, b1, b2, b3;
                ldsm4(b0, b1, b2, b3, wa + jp * (32 * SP) + 32 * s);
                mma16(acc[0][2 * jp], A0[0], A0[1], A0[2], A0[3], b0, b1);
                mma16(acc[0][2 * jp + 1], A0[0], A0[1], A0[2], A0[3], b2, b3);
                mma16(acc[1][2 * jp], A1[0], A1[1], A1[2], A1[3], b0, b1);
                mma16(acc[1][2 * jp + 1], A1[0], A1[1], A1[2], A1[3], b2, b3);
            }
        }
    }

    #pragma unroll
    for (int n = 0; n < 8; n++) {
        int col = n0 + 8 * n + 2 * c4;
        float b0v = B[col], b1v = B[col + 1];
        size_t base = (size_t)(col >> 6) * HW;
        #pragma unroll
        for (int m = 0; m < 2; m++) {
            int mr0 = m0 + rb + 16 * m + g, mr1 = mr0 + 8;
            *(__half2*)(dst + (base + mr0) * HD + (col & 63)) =
                __floats2half2_rn((acc[m][n][0] + b0v) * scale,
                                  (acc[m][n][1] + b1v) * scale);
            *(__half2*)(dst + (base + mr1) * HD + (col & 63)) =
                __floats2half2_rn((acc[m][n][2] + b0v) * scale,
                                  (acc[m][n][3] + b1v) * scale);
        }
    }
}

// ---------------- output projection (fp16 mma + ldmatrix, fp32 out) ----------
__global__ void __launch_bounds__(256, 2) projout_kernel(
    const float* __restrict__ W, const float* __restrict__ B,
    float* __restrict__ Yout)
{
    extern __shared__ __half smh[];
    __half* Xs = smh;
    __half* Ws = smh + 256 * SP;

    int tid = threadIdx.x;
    int warp = tid >> 5, lane = tid & 31, g = lane >> 2, c4 = lane & 3;
    int m0 = blockIdx.y * 256, n0 = blockIdx.x * 64;
    int rb = warp << 5;

    uint32_t sb = smem_u32(smh);
    uint32_t xa0 = sb + (uint32_t)((rb + (lane & 15)) * SP + ((lane & 16) >> 1)) * 2;
    uint32_t xa1 = xa0 + 16 * SP * 2;
    uint32_t wa = sb + (uint32_t)(256 * SP + ((lane & 7) + ((lane & 16) >> 1)) * SP
                                  + (lane & 8)) * 2;

    float acc[2][8][4] = {};

    for (int k0 = 0; k0 < CC; k0 += 64) {
        __syncthreads();
        #pragma unroll
        for (int i = 0; i < 8; i++) {
            int idx = tid + i * 256;
            int row = idx >> 3, j = idx & 7;
            *(uint4*)(Xs + row * SP + 8 * j) =
                *(const uint4*)(g_att_h + (size_t)(m0 + row) * CC + k0 + 8 * j);
        }
        #pragma unroll
        for (int i = 0; i < 4; i++) {
            int idx = tid + i * 256;
            int row = idx >> 4, j = idx & 15;
            float4 v = *(const float4*)(W + (size_t)(n0 + row) * CC + k0 + 4 * j);
            uint2 st;
            st.x = pack_h2(v.x, v.y); st.y = pack_h2(v.z, v.w);
            *(uint2*)(Ws + row * SP + 4 * j) = st;
        }
        __syncthreads();

        #pragma unroll
        for (int s = 0; s < 4; s++) {
            uint32_t A0[4], A1[4];
            ldsm4(A0[0], A0[1], A0[2], A0[3], xa0 + 32 * s);
            ldsm4(A1[0], A1[1], A1[2], A1[3], xa1 + 32 * s);
            #pragma unroll
            for (int jp = 0; jp < 4; jp++) {
                uint32_t b0, b1, b2, b3;
                ldsm4(b0, b1, b2, b3, wa + jp * (32 * SP) + 32 * s);
                mma16(acc[0][2 * jp], A0[0], A0[1], A0[2], A0[3], b0, b1);
                mma16(acc[0][2 * jp + 1], A0[0], A0[1], A0[2], A0[3], b2, b3);
                mma16(acc[1][2 * jp], A1[0], A1[1], A1[2], A1[3], b0, b1);
                mma16(acc[1][2 * jp + 1], A1[0], A1[1], A1[2], A1[3], b2, b3);
            }
        }
    }

    #pragma unroll
    for (int n = 0; n < 8; n++) {
        int col = n0 + 8 * n + 2 * c4;
        float b0v = B[col], b1v = B[col + 1];
        #pragma unroll
        for (int m = 0; m < 2; m++) {
            int mr0 = m0 + rb + 16 * m + g, mr1 = mr0 + 8;
            *(float2*)(Yout + (size_t)mr0 * CC + col) =
                make_float2(acc[m][n][0] + b0v, acc[m][n][1] + b1v);
            *(float2*)(Yout + (size_t)mr1 * CC + col) =
                make_float2(acc[m][n][2] + b0v, acc[m][n][3] + b1v);
        }
    }
}

// ---------------- decomposed rel-pos bias (fp16 mma) -------------------------
__global__ void __launch_bounds__(128) relpos_kernel(
    const float* __restrict__ rph, const float* __restrict__ rpw)
{
    __shared__ __half Qs[64 * SP];
    __shared__ __half Rs[64 * SP];
    int axis = blockIdx.z, head = blockIdx.y, a0 = blockIdx.x;
    int tid = threadIdx.x;
    int warp = tid >> 5, lane = tid & 31, g = lane >> 2, c4 = lane & 3;

    const float* rp = (axis == 0) ? rph : rpw;
    #pragma unroll
    for (int i = 0; i < 4; i++) {
        int idx = tid + i * 128;
        int row = idx >> 3, j = idx & 7;
        int tok = (axis == 0) ? (a0 * 64 + row) : (row * 64 + a0);
        *(uint4*)(Qs + row * SP + 8 * j) =
            *(const uint4*)(g_Q + ((size_t)head * HW + tok) * HD + 8 * j);
    }
    #pragma unroll
    for (int i = 0; i < 8; i++) {
        int idx = tid + i * 128;
        int row = idx >> 4, j = idx & 15;
        float4 v = *(const float4*)(rp + (size_t)(a0 - row + 63) * HD + 4 * j);
        uint2 st;
        st.x = pack_h2(v.x, v.y); st.y = pack_h2(v.z, v.w);
        *(uint2*)(Rs + row * SP + 4 * j) = st;
    }
    __syncthreads();

    uint32_t sq = smem_u32(Qs), sr = smem_u32(Rs);
    int r0 = warp * 16 + g, r1 = r0 + 8;
    uint32_t qa = sq + (uint32_t)((warp * 16 + (lane & 15)) * SP + ((lane & 16) >> 1)) * 2;
    uint32_t ra = sr + (uint32_t)(((lane & 7) + ((lane & 16) >> 1)) * SP + (lane & 8)) * 2;

    float acc[8][4] = {};
    #pragma unroll
    for (int s = 0; s < 4; s++) {
        uint32_t a0r, a1r, a2r, a3r;
        ldsm4(a0r, a1r, a2r, a3r, qa + 32 * s);
        #pragma unroll
        for (int jp = 0; jp < 4; jp++) {
            uint32_t b0, b1, b2, b3;
            ldsm4(b0, b1, b2, b3, ra + jp * (32 * SP) + 32 * s);
            mma16(acc[2 * jp], a0r, a1r, a2r, a3r, b0, b1);
            mma16(acc[2 * jp + 1], a0r, a1r, a2r, a3r, b2, b3);
        }
    }

    #pragma unroll
    for (int n = 0; n < 8; n++) {
        int k = 8 * n + 2 * c4;
        float v00 = acc[n][0] * 8.f, v01 = acc[n][1] * 8.f;
        float v10 = acc[n][2] * 8.f, v11 = acc[n][3] * 8.f;
        if (axis == 0) {
            int t0 = a0 * 64 + r0, t1 = a0 * 64 + r1;
            g_relh[((size_t)head * HD + k) * HW + t0] = v00;
            g_relh[((size_t)head * HD + k + 1) * HW + t0] = v01;
            g_relh[((size_t)head * HD + k) * HW + t1] = v10;
            g_relh[((size_t)head * HD + k + 1) * HW + t1] = v11;
        } else {
            int t0 = r0 * 64 + a0, t1 = r1 * 64 + a0;
            *(__half2*)(g_relw + ((size_t)head * HW + t0) * HD + k) =
                __floats2half2_rn(v00, v01);
            *(__half2*)(g_relw + ((size_t)head * HW + t1) * HD + k) =
                __floats2half2_rn(v10, v11);
        }
    }
}

// ---------------- flash attention: fused per-key-chunk QK->ex2->PV -----------
// smem halves: Qs[128*SP] Bws[128*SP] K[2][64*SP] V[2][64*SP] = 73728 B.
__global__ void __launch_bounds__(256, 2) attnmma_kernel()
{
    extern __shared__ __half smh[];
    __half* Qs  = smh;                   // [128][SP]
    __half* Bws = Qs + 128 * SP;         // [128][SP]
    const int KOFF = 256 * SP;           // K stages at 256*SP, 320*SP
    const int VOFF = 384 * SP;           // V stages at 384*SP, 448*SP

    int tid = threadIdx.x;
    int warp = tid >> 5, lane = tid & 31, g = lane >> 2, c4 = lane & 3;
    int head = blockIdx.y, q0 = blockIdx.x * 128;
    int r0 = warp * 16 + g, r1 = r0 + 8;

    uint32_t sb = smem_u32(smh);
    uint32_t qa = sb + (uint32_t)((warp * 16 + (lane & 15)) * SP + ((lane & 16) >> 1)) * 2;
    uint32_t ka_b = sb + (uint32_t)(KOFF + ((lane & 7) + ((lane & 16) >> 1)) * SP
                                    + (lane & 8)) * 2;
    uint32_t va_b = sb + (uint32_t)(VOFF + (lane & 15) * SP + ((lane & 16) >> 1)) * 2;

    int r_st = tid >> 3, j_st = tid & 7;
    size_t hb = (size_t)head * HW;

    // ---- tile 0 cp.async into stage 0, then stage Q/Bws ----
    #pragma unroll
    for (int i = 0; i < 2; i++) {
        int row = r_st + 32 * i;
        uint32_t dk = sb + (uint32_t)(KOFF + row * SP + 8 * j_st) * 2;
        uint32_t dv = sb + (uint32_t)(VOFF + row * SP + 8 * j_st) * 2;
        CP16(dk, g_K + (hb + row) * HD + 8 * j_st);
        CP16(dv, g_V + (hb + row) * HD + 8 * j_st);
    }
    CP_COMMIT();

    size_t qb = hb + q0;
    #pragma unroll
    for (int i = 0; i < 4; i++) {
        int idx = tid + i * 256;
        int row = idx >> 3, j = idx & 7;
        *(uint4*)(Qs + row * SP + 8 * j) =
            *(const uint4*)(g_Q + (qb + row) * HD + 8 * j);
        *(uint4*)(Bws + row * SP + 8 * j) =
            *(const uint4*)(g_relw + (qb + row) * HD + 8 * j);
    }

    const float* rh0 = g_relh + (size_t)head * HD * HW + q0;
    float nbh0 = rh0[r0], nbh1 = rh0[r1];

    float O[8][4] = {};
    float l0 = 0.f, l1 = 0.f;

    for (int kt = 0; kt < HW / 64; kt++) {
        int p = kt & 1;
        __syncthreads();   // all warps done reading stage p^1 (tile kt-1)
        if (kt + 1 < HW / 64) {
            size_t kb = hb + (size_t)(kt + 1) * 64;
            int st = (p ^ 1) * 64 * SP;
            #pragma unroll
            for (int i = 0; i < 2; i++) {
                int row = r_st + 32 * i;
                uint32_t dk = sb + (uint32_t)(KOFF + st + row * SP + 8 * j_st) * 2;
                uint32_t dv = sb + (uint32_t)(VOFF + st + row * SP + 8 * j_st) * 2;
                CP16(dk, g_K + (kb + row) * HD + 8 * j_st);
                CP16(dv, g_V + (kb + row) * HD + 8 * j_st);
            }
            CP_COMMIT();
            CP_WAIT(1);
        } else {
            CP_WAIT(0);
        }
        float bh0 = nbh0, bh1 = nbh1;
        __syncthreads();   // stage p visible

        if (kt + 1 < HW / 64) {
            const float* rh = g_relh + ((size_t)head * HD + kt + 1) * HW + q0;
            nbh0 = rh[r0]; nbh1 = rh[r1];
        }

        uint32_t ka = ka_b + (uint32_t)(p * 64 * SP) * 2;
        uint32_t va = va_b + (uint32_t)(p * 64 * SP) * 2;

        // ---- Q A-frags (k-steps 0..3), loaded once per tile ----
        uint32_t aq[4][4];
        #pragma unroll
        for (int s = 0; s < 4; s++)
            ldsm4(aq[s][0], aq[s][1], aq[s][2], aq[s][3], qa + 32 * s);

        // ---- fused per-key-chunk pipeline: QK(jp) -> ex2 -> PV(jp) ----
        #pragma unroll
        for (int jp = 0; jp < 4; jp++) {
            // S for n-blocks 2jp (cols 16jp+2c4) and 2jp+1 (cols +8)
            float Sa[4], Sb[4];
            {
                int col = 16 * jp + 2 * c4;
                float2 wa0 = __half22float2(*(const __half2*)(Bws + r0 * SP + col));
                float2 wa1 = __half22float2(*(const __half2*)(Bws + r1 * SP + col));
                float2 wb0 = __half22float2(*(const __half2*)(Bws + r0 * SP + col + 8));
                float2 wb1 = __half22float2(*(const __half2*)(Bws + r1 * SP + col + 8));
                Sa[0] = bh0 + wa0.x; Sa[1] = bh0 + wa0.y;
                Sa[2] = bh1 + wa1.x; Sa[3] = bh1 + wa1.y;
                Sb[0] = bh0 + wb0.x; Sb[1] = bh0 + wb0.y;
                Sb[2] = bh1 + wb1.x; Sb[3] = bh1 + wb1.y;
            }
            #pragma unroll
            for (int s = 0; s < 4; s++) {
                uint32_t b0, b1, b2, b3;
                ldsm4(b0, b1, b2, b3, ka + jp * (32 * SP) + 32 * s);
                mma16(Sa, aq[s][0], aq[s][1], aq[s][2], aq[s][3], b0, b1);
                mma16(Sb, aq[s][0], aq[s][1], aq[s][2], aq[s][3], b2, b3);
            }

            // ex2 + pack (A-frags for PV chunk jp)
            float pa0 = ex2f(Sa[0]), pa1 = ex2f(Sa[1]);
            float pa2 = ex2f(Sa[2]), pa3 = ex2f(Sa[3]);
            float pb0 = ex2f(Sb[0]), pb1 = ex2f(Sb[1]);
            float pb2 = ex2f(Sb[2]), pb3 = ex2f(Sb[3]);
            l0 += pa0 + pa1 + pb0 + pb1;
            l1 += pa2 + pa3 + pb2 + pb3;
            uint32_t h0a = pack_h2(pa0, pa1), h1a = pack_h2(pa2, pa3);
            uint32_t h0b = pack_h2(pb0, pb1), h1b = pack_h2(pb2, pb3);

            // PV: O += P[keys 16jp..16jp+15] @ V
            #pragma unroll
            for (int j2 = 0; j2 < 4; j2++) {
                uint32_t b0, b1, b2, b3;
                ldsm4t(b0, b1, b2, b3, va + jp * (32 * SP) + j2 * 32);
                mma16(O[2 * j2], h0a, h1a, h0b, h1b, b0, b1);
                mma16(O[2 * j2 + 1], h0a, h1a, h0b, h1b, b2, b3);
            }
        }
    }

    // final l reduction across the quad
    l0 += __shfl_xor_sync(0xffffffffu, l0, 1);
    l0 += __shfl_xor_sync(0xffffffffu, l0, 2);
    l1 += __shfl_xor_sync(0xffffffffu, l1, 1);
    l1 += __shfl_xor_sync(0xffffffffu, l1, 2);

    float inv0 = 1.0f / l0, inv1 = 1.0f / l1;
    #pragma unroll
    for (int n = 0; n < 8; n++) {
        int d = 8 * n + 2 * c4;
        *(__half2*)(g_att_h + (size_t)(q0 + r0) * CC + head * HD + d) =
            __floats2half2_rn(O[n][0] * inv0, O[n][1] * inv0);
        *(__half2*)(g_att_h + (size_t)(q0 + r1) * CC + head * HD + d) =
            __floats2half2_rn(O[n][2] * inv1, O[n][3] * inv1);
    }
}

// ---------------- launch -----------------------------------------------------
extern "C" void kernel_launch(void* const* d_in, const int* in_sizes, int n_in,
                              void* d_out, int out_size)
{
    const float* hs  = (const float*)d_in[0];
    const float* w_q = (const float*)d_in[1];
    const float* b_q = (const float*)d_in[2];
    const float* w_k = (const float*)d_in[3];
    const float* b_k = (const float*)d_in[4];
    const float* w_v = (const float*)d_in[5];
    const float* b_v = (const float*)d_in[6];
    const float* w_o = (const float*)d_in[7];
    const float* b_o = (const float*)d_in[8];
    const float* rph = (const float*)d_in[9];
    const float* rpw = (const float*)d_in[10];
    float* out = (float*)d_out;

    int proj_smem = (256 * SP + 64 * SP) * (int)sizeof(__half);           // 46080 B
    int att_smem  = (2 * 128 * SP + 4 * 64 * SP) * (int)sizeof(__half);   // 73728 B

    cudaFuncSetAttribute(projqkv_kernel, cudaFuncAttributeMaxDynamicSharedMemorySize, proj_smem);
    cudaFuncSetAttribute(projout_kernel, cudaFuncAttributeMaxDynamicSharedMemorySize, proj_smem);
    cudaFuncSetAttribute(attnmma_kernel, cudaFuncAttributeMaxDynamicSharedMemorySize, att_smem);

    cvt_kernel<<<HW * CC / 1024, 256>>>(hs);

    projqkv_kernel<<<dim3(CC / 64, HW / 256, 3), 256, proj_smem>>>(
        w_q, b_q, w_k, b_k, w_v, b_v);

    relpos_kernel<<<dim3(64, NHEADS, 2), 128>>>(rph, rpw);

    attnmma_kernel<<<dim3(HW / 128, NHEADS), 256, att_smem>>>();

    projout_kernel<<<dim3(CC / 64, HW / 256), 256, proj_smem>>>(w_o, b_o, out);
}